// round 1
// baseline (speedup 1.0000x reference)
#include <cuda_runtime.h>
#include <math.h>
#include <stdint.h>

#define BB  8
#define CC  256
#define MIDD 32
#define NN  4096

// ---------------- scratch (static device globals: allocation-free) ----------
__device__ float g_A  [BB][MIDD*NN];          // 4 MB   a projection [mid][n]
__device__ float g_Bm [BB][MIDD*NN];          // 4 MB   b projection [mid][n]
__device__ float g_PT [(size_t)BB*NN*NN];     // 537 MB p^T : [b][j][i]
__device__ float g_mx [BB*NN];                // col max  m[j]
__device__ float g_Zs [BB*NN];                // col sumexp Z[j]
__device__ float g_Cs [BB][CC*NN];            // 33.5 MB  c' = (WcX+bc)/Z  [k][j]
__device__ float g_O  [BB][NN*CC];            // 33.5 MB  out [i][k] flat (== Y [c][n])

// ---------------- K1: A = WaX+ba, B = WbX+bb --------------------------------
__global__ void k_ab(const float* __restrict__ x,
                     const float* __restrict__ wa, const float* __restrict__ ba,
                     const float* __restrict__ wb, const float* __restrict__ bb)
{
    __shared__ float ws[MIDD*CC];
    __shared__ float bs[MIDD];
    const int b = blockIdx.y;
    const int which = blockIdx.z;
    const float* w    = which ? wb : wa;
    const float* bias = which ? bb : ba;
    float* outp       = which ? g_Bm[b] : g_A[b];

    for (int i = threadIdx.x; i < MIDD*CC; i += 256) ws[i] = w[i];
    if (threadIdx.x < MIDD) bs[threadIdx.x] = bias[threadIdx.x];
    __syncthreads();

    const int n = blockIdx.x*256 + threadIdx.x;
    const float* xb = x + (size_t)b*CC*NN;
    float acc[MIDD];
    #pragma unroll
    for (int m = 0; m < MIDD; m++) acc[m] = bs[m];
    for (int c = 0; c < CC; c++) {
        float xv = xb[c*NN + n];
        #pragma unroll
        for (int m = 0; m < MIDD; m++) acc[m] += ws[m*CC + c] * xv;
    }
    #pragma unroll
    for (int m = 0; m < MIDD; m++) outp[m*NN + n] = acc[m];
}

// ---------------- K2: PT[j][i] = sum_m B[m][j]*A[m][i] ----------------------
__launch_bounds__(256, 2)
__global__ void k_pt()
{
    __shared__ float As[MIDD][128];
    __shared__ float Bs[MIDD][128];
    const int b  = blockIdx.z;
    const int j0 = blockIdx.y * 128;
    const int i0 = blockIdx.x * 128;
    const float* A  = g_A [b];
    const float* Bm = g_Bm[b];

    for (int idx = threadIdx.x; idx < MIDD*128; idx += 256) {
        int m = idx >> 7, t = idx & 127;
        As[m][t] = A [m*NN + i0 + t];
        Bs[m][t] = Bm[m*NN + j0 + t];
    }
    __syncthreads();

    const int ti = threadIdx.x & 15;   // i micro
    const int tj = threadIdx.x >> 4;   // j micro
    float acc[8][8];
    #pragma unroll
    for (int u = 0; u < 8; u++)
        #pragma unroll
        for (int v = 0; v < 8; v++) acc[u][v] = 0.f;

    #pragma unroll
    for (int m = 0; m < MIDD; m++) {
        float bj[8], ai[8];
        #pragma unroll
        for (int u = 0; u < 8; u++) { bj[u] = Bs[m][tj*8+u]; ai[u] = As[m][ti*8+u]; }
        #pragma unroll
        for (int u = 0; u < 8; u++)
            #pragma unroll
            for (int v = 0; v < 8; v++) acc[u][v] += bj[u] * ai[v];
    }

    float* PT = &g_PT[(size_t)b*NN*NN];
    #pragma unroll
    for (int u = 0; u < 8; u++) {
        size_t rowoff = (size_t)(j0 + tj*8 + u) * NN + i0 + ti*8;
        #pragma unroll
        for (int v = 0; v < 8; v++) PT[rowoff + v] = acc[u][v];
    }
}

// ---------------- K3: per-row (== softmax column) max & sum-exp -------------
__global__ void k_stats()
{
    const int b = blockIdx.y;
    const int j = blockIdx.x;
    const float* row = &g_PT[((size_t)b*NN + j) * NN];
    const int tid = threadIdx.x;

    float v[16];
    #pragma unroll
    for (int u = 0; u < 16; u++) v[u] = row[tid + u*256];

    float mx = v[0];
    #pragma unroll
    for (int u = 1; u < 16; u++) mx = fmaxf(mx, v[u]);

    __shared__ float red[256];
    red[tid] = mx; __syncthreads();
    for (int s = 128; s > 0; s >>= 1) {
        if (tid < s) red[tid] = fmaxf(red[tid], red[tid+s]);
        __syncthreads();
    }
    mx = red[0];
    __syncthreads();

    float sm = 0.f;
    #pragma unroll
    for (int u = 0; u < 16; u++) sm += __expf(v[u] - mx);
    red[tid] = sm; __syncthreads();
    for (int s = 128; s > 0; s >>= 1) {
        if (tid < s) red[tid] += red[tid+s];
        __syncthreads();
    }
    if (tid == 0) { g_mx[b*NN + j] = mx; g_Zs[b*NN + j] = red[0]; }
}

// ---------------- K4: Cs[k][j] = (WcX+bc)[k][j] / Z[j] ----------------------
__global__ void k_c(const float* __restrict__ x,
                    const float* __restrict__ wc, const float* __restrict__ bc)
{
    __shared__ float ws[32*CC];
    const int b  = blockIdx.y;
    const int kc = blockIdx.z;          // chunk of 32 output channels
    for (int i = threadIdx.x; i < 32*CC; i += 256) ws[i] = wc[kc*32*CC + i];
    __syncthreads();

    const int j = blockIdx.x*256 + threadIdx.x;
    const float invZ = 1.f / g_Zs[b*NN + j];
    const float* xb = x + (size_t)b*CC*NN;

    float acc[32];
    #pragma unroll
    for (int m = 0; m < 32; m++) acc[m] = bc[kc*32 + m];
    for (int c = 0; c < CC; c++) {
        float xv = xb[c*NN + j];
        #pragma unroll
        for (int m = 0; m < 32; m++) acc[m] += ws[m*CC + c] * xv;
    }
    float* Cb = g_Cs[b];
    #pragma unroll
    for (int m = 0; m < 32; m++) Cb[(kc*32 + m)*NN + j] = acc[m] * invZ;
}

// ---------------- K5: out[i][k] = sum_j exp(PT[j][i]-m[j]) * Cs[k][j] -------
__launch_bounds__(256, 2)
__global__ void k_out()
{
    __shared__ float Es [32][128];      // exp(p - m) tile, [j][i]
    __shared__ float Css[32][132];      // Cs tile transposed, [j][k] (padded)
    const int b  = blockIdx.z;
    const int i0 = blockIdx.y * 128;
    const int k0 = blockIdx.x * 128;
    const float* PT   = &g_PT[(size_t)b*NN*NN];
    const float* Cs   = g_Cs[b];
    const float* mrow = &g_mx[b*NN];

    const int ti = threadIdx.x & 15;    // i micro
    const int tk = threadIdx.x >> 4;    // k micro
    float acc[8][8];
    #pragma unroll
    for (int u = 0; u < 8; u++)
        #pragma unroll
        for (int v = 0; v < 8; v++) acc[u][v] = 0.f;

    for (int j0 = 0; j0 < NN; j0 += 32) {
        __syncthreads();  // previous compute done before refill
        for (int idx = threadIdx.x; idx < 32*128; idx += 256) {
            int j = idx >> 7, i = idx & 127;
            float mv = __ldg(mrow + j0 + j);
            Es[j][i] = __expf(PT[(size_t)(j0 + j)*NN + i0 + i] - mv);
        }
        for (int idx = threadIdx.x; idx < 128*32; idx += 256) {
            int k = idx >> 5, j = idx & 31;
            Css[j][k] = Cs[(k0 + k)*NN + j0 + j];
        }
        __syncthreads();

        #pragma unroll
        for (int j = 0; j < 32; j++) {
            float e[8], cv[8];
            #pragma unroll
            for (int u = 0; u < 8; u++) { e[u] = Es[j][ti*8+u]; cv[u] = Css[j][tk*8+u]; }
            #pragma unroll
            for (int u = 0; u < 8; u++)
                #pragma unroll
                for (int v = 0; v < 8; v++) acc[u][v] += e[u] * cv[v];
        }
    }

    float* Ob = g_O[b];
    #pragma unroll
    for (int u = 0; u < 8; u++) {
        int rowoff = (i0 + ti*8 + u) * CC + k0 + tk*8;
        #pragma unroll
        for (int v = 0; v < 8; v++) Ob[rowoff + v] = acc[u][v];
    }
}

// ---------------- K6: final = Wo(beta*Y + X) + bo ---------------------------
__global__ void k_final(const float* __restrict__ x,
                        const float* __restrict__ wo, const float* __restrict__ bo,
                        const float* __restrict__ beta, float* __restrict__ out)
{
    __shared__ float ws[32*CC];
    const int b  = blockIdx.y;
    const int kc = blockIdx.z;
    for (int i = threadIdx.x; i < 32*CC; i += 256) ws[i] = wo[kc*32*CC + i];
    __syncthreads();

    const int n = blockIdx.x*256 + threadIdx.x;
    const float bt = beta[0];
    const float* xb = x + (size_t)b*CC*NN;
    const float* Yb = g_O[b];           // flat reinterpret: Y[c][n] = Ob[c*NN+n]

    float acc[32];
    #pragma unroll
    for (int m = 0; m < 32; m++) acc[m] = bo[kc*32 + m];
    for (int c = 0; c < CC; c++) {
        float v = fmaf(bt, Yb[c*NN + n], xb[c*NN + n]);
        #pragma unroll
        for (int m = 0; m < 32; m++) acc[m] += ws[m*CC + c] * v;
    }
    #pragma unroll
    for (int m = 0; m < 32; m++)
        out[((size_t)b*CC + kc*32 + m)*NN + n] = acc[m];
}

// ---------------- launch ----------------------------------------------------
extern "C" void kernel_launch(void* const* d_in, const int* in_sizes, int n_in,
                              void* d_out, int out_size)
{
    const float* x    = (const float*)d_in[0];
    const float* wa   = (const float*)d_in[1];
    const float* ba   = (const float*)d_in[2];
    const float* wb   = (const float*)d_in[3];
    const float* bb   = (const float*)d_in[4];
    const float* wc   = (const float*)d_in[5];
    const float* bc   = (const float*)d_in[6];
    const float* wo   = (const float*)d_in[7];
    const float* bo   = (const float*)d_in[8];
    const float* beta = (const float*)d_in[9];
    float* out = (float*)d_out;

    k_ab   <<<dim3(NN/256, BB, 2),   256>>>(x, wa, ba, wb, bb);
    k_pt   <<<dim3(NN/128, NN/128, BB), 256>>>();
    k_stats<<<dim3(NN, BB),          256>>>();
    k_c    <<<dim3(NN/256, BB, CC/32), 256>>>(x, wc, bc);
    k_out  <<<dim3(CC/128, NN/128, BB), 256>>>();
    k_final<<<dim3(NN/256, BB, CC/32), 256>>>(x, wo, bo, beta, out);
}

// round 3
// speedup vs baseline: 1.9998x; 1.9998x over previous
#include <cuda_runtime.h>
#include <math.h>
#include <stdint.h>

#define BB  8
#define CC  256
#define MIDD 32
#define NN  4096

// ---------------- scratch ----------------------------------------------------
__device__ float g_A  [BB][MIDD*NN];
__device__ float g_Bm [BB][MIDD*NN];
__device__ float g_PT [(size_t)BB*NN*NN];     // p^T : [b][j][i]
__device__ float g_mx [BB*NN];
__device__ float g_Zs [BB*NN];
__device__ float g_Cs [BB][CC*NN];            // (WcX+bc)/Z  [k][j]
__device__ float g_O  [BB][NN*CC];            // out [i][k]  (== Y [c][n] flat)

// ---------------- K1: A = WaX+ba, B = WbX+bb ----------------------------------
__global__ void k_ab(const float* __restrict__ x,
                     const float* __restrict__ wa, const float* __restrict__ ba,
                     const float* __restrict__ wb, const float* __restrict__ bb)
{
    __shared__ float ws[MIDD*CC];
    __shared__ float bs[MIDD];
    const int b = blockIdx.y;
    const int which = blockIdx.z;
    const float* w    = which ? wb : wa;
    const float* bias = which ? bb : ba;
    float* outp       = which ? g_Bm[b] : g_A[b];

    for (int i = threadIdx.x; i < MIDD*CC; i += 256) ws[i] = w[i];
    if (threadIdx.x < MIDD) bs[threadIdx.x] = bias[threadIdx.x];
    __syncthreads();

    const int n = blockIdx.x*256 + threadIdx.x;
    const float* xb = x + (size_t)b*CC*NN;
    float acc[MIDD];
    #pragma unroll
    for (int m = 0; m < MIDD; m++) acc[m] = bs[m];
    for (int c = 0; c < CC; c++) {
        float xv = xb[c*NN + n];
        #pragma unroll
        for (int m = 0; m < MIDD; m++) acc[m] += ws[m*CC + c] * xv;
    }
    #pragma unroll
    for (int m = 0; m < MIDD; m++) outp[m*NN + n] = acc[m];
}

// ---------------- K2: PT[j][i] = sum_m B[m][j]*A[m][i] (fp32, exact) ----------
__launch_bounds__(256, 2)
__global__ void k_pt()
{
    __shared__ float As[MIDD][128];
    __shared__ float Bs[MIDD][128];
    const int b  = blockIdx.z;
    const int j0 = blockIdx.y * 128;
    const int i0 = blockIdx.x * 128;
    const float* A  = g_A [b];
    const float* Bm = g_Bm[b];

    for (int idx = threadIdx.x; idx < MIDD*128; idx += 256) {
        int m = idx >> 7, t = idx & 127;
        As[m][t] = A [m*NN + i0 + t];
        Bs[m][t] = Bm[m*NN + j0 + t];
    }
    __syncthreads();

    const int ti = threadIdx.x & 15;
    const int tj = threadIdx.x >> 4;
    float acc[8][8];
    #pragma unroll
    for (int u = 0; u < 8; u++)
        #pragma unroll
        for (int v = 0; v < 8; v++) acc[u][v] = 0.f;

    #pragma unroll
    for (int m = 0; m < MIDD; m++) {
        float bj[8], ai[8];
        #pragma unroll
        for (int u = 0; u < 8; u++) { bj[u] = Bs[m][tj*8+u]; ai[u] = As[m][ti*8+u]; }
        #pragma unroll
        for (int u = 0; u < 8; u++)
            #pragma unroll
            for (int v = 0; v < 8; v++) acc[u][v] += bj[u] * ai[v];
    }

    float* PT = &g_PT[(size_t)b*NN*NN];
    #pragma unroll
    for (int u = 0; u < 8; u++) {
        size_t rowoff = (size_t)(j0 + tj*8 + u) * NN + i0 + ti*8;
        #pragma unroll
        for (int v = 0; v < 8; v++) PT[rowoff + v] = acc[u][v];
    }
}

// ---------------- K3: per softmax-column max & sum-exp -------------------------
__global__ void k_stats()
{
    const int b = blockIdx.y;
    const int j = blockIdx.x;
    const float* row = &g_PT[((size_t)b*NN + j) * NN];
    const int tid = threadIdx.x;

    float v[16];
    #pragma unroll
    for (int u = 0; u < 16; u++) v[u] = row[tid + u*256];

    float mx = v[0];
    #pragma unroll
    for (int u = 1; u < 16; u++) mx = fmaxf(mx, v[u]);

    __shared__ float red[256];
    red[tid] = mx; __syncthreads();
    for (int s = 128; s > 0; s >>= 1) {
        if (tid < s) red[tid] = fmaxf(red[tid], red[tid+s]);
        __syncthreads();
    }
    mx = red[0];
    __syncthreads();

    float sm = 0.f;
    #pragma unroll
    for (int u = 0; u < 16; u++) sm += __expf(v[u] - mx);
    red[tid] = sm; __syncthreads();
    for (int s = 128; s > 0; s >>= 1) {
        if (tid < s) red[tid] += red[tid+s];
        __syncthreads();
    }
    if (tid == 0) { g_mx[b*NN + j] = mx; g_Zs[b*NN + j] = red[0]; }
}

// ---------------- K4: Cs[k][j] = (WcX+bc)[k][j] / Z[j]  (register-tiled) -------
__global__ void k_c(const float* __restrict__ x,
                    const float* __restrict__ wc, const float* __restrict__ bc)
{
    __shared__ float ws[32*CC];
    const int b  = blockIdx.y;
    const int kc = blockIdx.z;
    for (int i = threadIdx.x; i < 32*CC; i += 256) ws[i] = wc[kc*32*CC + i];
    __syncthreads();

    const int tx = threadIdx.x & 63;
    const int ty = threadIdx.x >> 6;
    const int n0 = blockIdx.x*256 + tx*4;
    const float* Z = &g_Zs[b*NN];
    float iz0 = 1.f/Z[n0], iz1 = 1.f/Z[n0+1], iz2 = 1.f/Z[n0+2], iz3 = 1.f/Z[n0+3];

    const float4* x4 = (const float4*)(x + (size_t)b*CC*NN);
    float a0[8], a1[8], a2[8], a3[8];
    #pragma unroll
    for (int m = 0; m < 8; m++) {
        float bv = bc[kc*32 + ty*8 + m];
        a0[m]=bv; a1[m]=bv; a2[m]=bv; a3[m]=bv;
    }
    #pragma unroll 4
    for (int c = 0; c < CC; c++) {
        float4 xv = x4[(c*NN + n0) >> 2];
        #pragma unroll
        for (int m = 0; m < 8; m++) {
            float w = ws[(ty*8+m)*CC + c];
            a0[m] += w*xv.x; a1[m] += w*xv.y; a2[m] += w*xv.z; a3[m] += w*xv.w;
        }
    }
    float* Cb = g_Cs[b];
    #pragma unroll
    for (int m = 0; m < 8; m++) {
        int k = kc*32 + ty*8 + m;
        float4 o = make_float4(a0[m]*iz0, a1[m]*iz1, a2[m]*iz2, a3[m]*iz3);
        *(float4*)(Cb + (size_t)k*NN + n0) = o;
    }
}

// ---------------- K5: mma.sync tf32: out[i][k] = sum_j E[i][j]*Cs[k][j] --------
// E[i][j] = exp(PT[j][i] - m[j]).  Block: M=128 (i), N=256 (all k), K-chunks 32.
// 512 threads = 16 warps as 2 (M) x 8 (N); warp tile 64x32 via m16n8k8 frags.
#define EPAD 36
#define ES_OFF 0
#define BS_OFF (128*EPAD*4)
#define KO_SMEM (128*EPAD*4 + 256*EPAD*4)   // 18432 + 36864 = 55296

__device__ __forceinline__ uint32_t to_tf32(float f) {
    uint32_t u;
    asm("cvt.rna.tf32.f32 %0, %1;" : "=r"(u) : "f"(f));
    return u;
}
__device__ __forceinline__ void mma16n8k8(float* c, const uint32_t* a, const uint32_t* b) {
    asm volatile(
        "mma.sync.aligned.m16n8k8.row.col.f32.tf32.tf32.f32 "
        "{%0,%1,%2,%3}, {%4,%5,%6,%7}, {%8,%9}, {%0,%1,%2,%3};"
        : "+f"(c[0]), "+f"(c[1]), "+f"(c[2]), "+f"(c[3])
        : "r"(a[0]), "r"(a[1]), "r"(a[2]), "r"(a[3]), "r"(b[0]), "r"(b[1]));
}

__global__ void __launch_bounds__(512, 1) k_out_mma()
{
    extern __shared__ float smf[];
    float* Es = smf;                    // [i:128][j:32] stride EPAD
    float* Bs = smf + 128*EPAD;         // [k:256][j:32] stride EPAD

    const int tid  = threadIdx.x;
    const int lane = tid & 31;
    const int warp = tid >> 5;
    const int wm   = warp & 1;          // 0..1  (M)
    const int wn   = warp >> 1;         // 0..7  (N)
    const int b    = blockIdx.y;
    const int i0   = blockIdx.x * 128;

    const float* PT   = &g_PT[(size_t)b*NN*NN];
    const float* Cs   = g_Cs[b];
    const float* mrow = &g_mx[b*NN];

    const int lr = lane >> 2;           // 0..7  row-in-frag
    const int lc = lane & 3;            // 0..3  col-in-frag

    float acc[4][4][4];
    #pragma unroll
    for (int mf = 0; mf < 4; mf++)
        #pragma unroll
        for (int nf = 0; nf < 4; nf++)
            #pragma unroll
            for (int q = 0; q < 4; q++) acc[mf][nf][q] = 0.f;

    for (int ch = 0; ch < NN/32; ch++) {
        const int j0 = ch * 32;
        __syncthreads();    // previous compute done before smem refill

        // stage E = exp(PT - m), tf32-rounded.  4096 elems, 8/thread.
        #pragma unroll
        for (int r = 0; r < 8; r++) {
            int id = tid + 512*r;
            int j = id >> 7, i = id & 127;
            float p = PT[(size_t)(j0 + j)*NN + i0 + i];
            float e = __expf(p - __ldg(mrow + j0 + j));
            Es[i*EPAD + j] = __uint_as_float(to_tf32(e));
        }
        // stage Cs, tf32-rounded. 8192 elems, 4 float4/thread.
        #pragma unroll
        for (int r = 0; r < 4; r++) {
            int id = tid + 512*r;
            int k = id >> 3, jq = id & 7;
            float4 v = *(const float4*)(Cs + (size_t)k*NN + j0 + jq*4);
            float* dst = Bs + k*EPAD + jq*4;
            dst[0] = __uint_as_float(to_tf32(v.x));
            dst[1] = __uint_as_float(to_tf32(v.y));
            dst[2] = __uint_as_float(to_tf32(v.z));
            dst[3] = __uint_as_float(to_tf32(v.w));
        }
        __syncthreads();

        #pragma unroll
        for (int ks = 0; ks < 4; ks++) {
            const int jb = ks * 8;
            uint32_t afr[4][4];
            #pragma unroll
            for (int mf = 0; mf < 4; mf++) {
                const float* ab = Es + (wm*64 + mf*16 + lr)*EPAD + jb + lc;
                afr[mf][0] = __float_as_uint(ab[0]);
                afr[mf][1] = __float_as_uint(ab[8*EPAD]);
                afr[mf][2] = __float_as_uint(ab[4]);
                afr[mf][3] = __float_as_uint(ab[8*EPAD + 4]);
            }
            uint32_t bfr[4][2];
            #pragma unroll
            for (int nf = 0; nf < 4; nf++) {
                const float* bb = Bs + (wn*32 + nf*8 + lr)*EPAD + jb + lc;
                bfr[nf][0] = __float_as_uint(bb[0]);
                bfr[nf][1] = __float_as_uint(bb[4]);
            }
            #pragma unroll
            for (int mf = 0; mf < 4; mf++)
                #pragma unroll
                for (int nf = 0; nf < 4; nf++)
                    mma16n8k8(acc[mf][nf], afr[mf], bfr[nf]);
        }
    }

    // epilogue: c0,c1 -> (row, 2lc..2lc+1), c2,c3 -> (row+8, ...)
    float* Ob = g_O[b];
    #pragma unroll
    for (int mf = 0; mf < 4; mf++) {
        int row0 = i0 + wm*64 + mf*16 + lr;
        #pragma unroll
        for (int nf = 0; nf < 4; nf++) {
            int col = wn*32 + nf*8 + 2*lc;
            *(float2*)(Ob + (size_t)row0*CC + col) =
                make_float2(acc[mf][nf][0], acc[mf][nf][1]);
            *(float2*)(Ob + (size_t)(row0+8)*CC + col) =
                make_float2(acc[mf][nf][2], acc[mf][nf][3]);
        }
    }
}

// ---------------- K6: final = Wo(beta*Y + X) + bo  (register-tiled) ------------
__global__ void k_final(const float* __restrict__ x,
                        const float* __restrict__ wo, const float* __restrict__ bo,
                        const float* __restrict__ beta, float* __restrict__ out)
{
    __shared__ float ws[32*CC];
    const int b  = blockIdx.y;
    const int kc = blockIdx.z;
    for (int i = threadIdx.x; i < 32*CC; i += 256) ws[i] = wo[kc*32*CC + i];
    __syncthreads();

    const int tx = threadIdx.x & 63;
    const int ty = threadIdx.x >> 6;
    const int n0 = blockIdx.x*256 + tx*4;
    const float bt = beta[0];
    const float4* x4 = (const float4*)(x + (size_t)b*CC*NN);
    const float4* y4 = (const float4*)(g_O[b]);   // flat: Y[c][n] = O[c*NN+n]

    float a0[8], a1[8], a2[8], a3[8];
    #pragma unroll
    for (int m = 0; m < 8; m++) {
        float bv = bo[kc*32 + ty*8 + m];
        a0[m]=bv; a1[m]=bv; a2[m]=bv; a3[m]=bv;
    }
    #pragma unroll 4
    for (int c = 0; c < CC; c++) {
        float4 xv = x4[(c*NN + n0) >> 2];
        float4 yv = y4[(c*NN + n0) >> 2];
        float v0 = fmaf(bt, yv.x, xv.x);
        float v1 = fmaf(bt, yv.y, xv.y);
        float v2 = fmaf(bt, yv.z, xv.z);
        float v3 = fmaf(bt, yv.w, xv.w);
        #pragma unroll
        for (int m = 0; m < 8; m++) {
            float w = ws[(ty*8+m)*CC + c];
            a0[m] += w*v0; a1[m] += w*v1; a2[m] += w*v2; a3[m] += w*v3;
        }
    }
    #pragma unroll
    for (int m = 0; m < 8; m++) {
        int k = kc*32 + ty*8 + m;
        *(float4*)(out + ((size_t)b*CC + k)*NN + n0) = make_float4(a0[m], a1[m], a2[m], a3[m]);
    }
}

// ---------------- launch --------------------------------------------------------
extern "C" void kernel_launch(void* const* d_in, const int* in_sizes, int n_in,
                              void* d_out, int out_size)
{
    const float* x    = (const float*)d_in[0];
    const float* wa   = (const float*)d_in[1];
    const float* ba   = (const float*)d_in[2];
    const float* wb   = (const float*)d_in[3];
    const float* bb   = (const float*)d_in[4];
    const float* wc   = (const float*)d_in[5];
    const float* bc   = (const float*)d_in[6];
    const float* wo   = (const float*)d_in[7];
    const float* bo   = (const float*)d_in[8];
    const float* beta = (const float*)d_in[9];
    float* out = (float*)d_out;

    cudaFuncSetAttribute(k_out_mma, cudaFuncAttributeMaxDynamicSharedMemorySize, KO_SMEM);

    k_ab    <<<dim3(NN/256, BB, 2),      256>>>(x, wa, ba, wb, bb);
    k_pt    <<<dim3(NN/128, NN/128, BB), 256>>>();
    k_stats <<<dim3(NN, BB),             256>>>();
    k_c     <<<dim3(NN/256, BB, CC/32),  256>>>(x, wc, bc);
    k_out_mma<<<dim3(NN/128, BB), 512, KO_SMEM>>>();
    k_final <<<dim3(NN/256, BB, CC/32),  256>>>(x, wo, bo, beta, out);
}

// round 4
// speedup vs baseline: 3.3232x; 1.6618x over previous
#include <cuda_runtime.h>
#include <cuda_bf16.h>
#include <math.h>
#include <stdint.h>

#define BB  8
#define CC  256
#define MIDD 32
#define NN  4096

// ---------------- scratch ----------------------------------------------------
__device__ float g_A  [BB][MIDD*NN];
__device__ float g_Bm [BB][MIDD*NN];
__device__ __nv_bfloat16 g_E[(size_t)BB*NN*NN];   // 268 MB, E[i][j] = exp(p-m)
__device__ float g_mx [BB];                       // per-batch softmax upper bound
__device__ float g_Zs [BB*NN];                    // Z[j] (atomic accumulated)
__device__ __nv_bfloat16 g_CsH[BB][CC*NN];        // (WcX+bc)/Z  [k][j] bf16
__device__ float g_O  [BB][NN*CC];                // out [i][k] (== Y[c][n] flat)

__device__ __forceinline__ uint32_t smem_u32(const void* p) {
    uint32_t a;
    asm("{ .reg .u64 t; cvta.to.shared.u64 t, %1; cvt.u32.u64 %0, t; }" : "=r"(a) : "l"(p));
    return a;
}
__device__ __forceinline__ uint32_t pk_bf2(float a, float b) {
    __nv_bfloat162 h = __floats2bfloat162_rn(a, b);
    return *(uint32_t*)&h;
}
#define CP16(dst, src) asm volatile("cp.async.cg.shared.global [%0], [%1], 16;" :: "r"(dst), "l"(src))
#define CP_COMMIT()    asm volatile("cp.async.commit_group;" ::: "memory")
#define CP_WAIT(n)     asm volatile("cp.async.wait_group %0;" :: "n"(n) : "memory")

__device__ __forceinline__ void mma_bf16(float* c, const uint32_t* a, const uint32_t* b) {
    asm volatile(
        "mma.sync.aligned.m16n8k16.row.col.f32.bf16.bf16.f32 "
        "{%0,%1,%2,%3}, {%4,%5,%6,%7}, {%8,%9}, {%0,%1,%2,%3};"
        : "+f"(c[0]), "+f"(c[1]), "+f"(c[2]), "+f"(c[3])
        : "r"(a[0]), "r"(a[1]), "r"(a[2]), "r"(a[3]), "r"(b[0]), "r"(b[1]));
}

// ---------------- K0: zero Z ---------------------------------------------------
__global__ void k_zero() {
    int i = blockIdx.x*1024 + threadIdx.x;
    if (i < BB*NN) g_Zs[i] = 0.f;
}

// ---------------- K1: A = WaX+ba, B = WbX+bb ----------------------------------
__global__ void k_ab(const float* __restrict__ x,
                     const float* __restrict__ wa, const float* __restrict__ ba,
                     const float* __restrict__ wb, const float* __restrict__ bb)
{
    __shared__ float ws[MIDD*CC];
    __shared__ float bs[MIDD];
    const int b = blockIdx.y;
    const int which = blockIdx.z;
    const float* w    = which ? wb : wa;
    const float* bias = which ? bb : ba;
    float* outp       = which ? g_Bm[b] : g_A[b];

    for (int i = threadIdx.x; i < MIDD*CC; i += 256) ws[i] = w[i];
    if (threadIdx.x < MIDD) bs[threadIdx.x] = bias[threadIdx.x];
    __syncthreads();

    const int n = blockIdx.x*256 + threadIdx.x;
    const float* xb = x + (size_t)b*CC*NN;
    float acc[MIDD];
    #pragma unroll
    for (int m = 0; m < MIDD; m++) acc[m] = bs[m];
    for (int c = 0; c < CC; c++) {
        float xv = xb[c*NN + n];
        #pragma unroll
        for (int m = 0; m < MIDD; m++) acc[m] += ws[m*CC + c] * xv;
    }
    #pragma unroll
    for (int m = 0; m < MIDD; m++) outp[m*NN + n] = acc[m];
}

// ---------------- K2: per-batch bound m = max||a|| * max||b|| -------------------
__global__ void k_norm() {
    const int b = blockIdx.x;
    const int t = threadIdx.x;
    const float* A  = g_A [b];
    const float* Bm = g_Bm[b];
    float ma = 0.f, mb = 0.f;
    for (int i = t; i < NN; i += 256) {
        float sa = 0.f, sb = 0.f;
        #pragma unroll
        for (int m = 0; m < MIDD; m++) {
            float av = A [m*NN + i]; sa += av*av;
            float bv = Bm[m*NN + i]; sb += bv*bv;
        }
        ma = fmaxf(ma, sa); mb = fmaxf(mb, sb);
    }
    __shared__ float ra[256], rb[256];
    ra[t] = ma; rb[t] = mb; __syncthreads();
    for (int s = 128; s > 0; s >>= 1) {
        if (t < s) { ra[t] = fmaxf(ra[t], ra[t+s]); rb[t] = fmaxf(rb[t], rb[t+s]); }
        __syncthreads();
    }
    if (t == 0) g_mx[b] = sqrtf(ra[0]) * sqrtf(rb[0]);
}

// ---------------- K3: E[i][j] = exp(p - m) bf16, Z[j] += sum_i E ---------------
__launch_bounds__(256, 2)
__global__ void k_pt_e()
{
    __shared__ float As[MIDD][128];   // i side
    __shared__ float Bs[MIDD][128];   // j side
    __shared__ float Zsm[128];
    const int b  = blockIdx.z;
    const int i0 = blockIdx.y * 128;
    const int j0 = blockIdx.x * 128;
    const float* A  = g_A [b];
    const float* Bm = g_Bm[b];
    const int tid = threadIdx.x;

    for (int idx = tid; idx < MIDD*128; idx += 256) {
        int m = idx >> 7, t = idx & 127;
        As[m][t] = A [m*NN + i0 + t];
        Bs[m][t] = Bm[m*NN + j0 + t];
    }
    if (tid < 128) Zsm[tid] = 0.f;
    __syncthreads();

    const int tj  = tid & 15;   // j micro lane
    const int tiq = tid >> 4;   // i micro group
    float acc[8][8];
    #pragma unroll
    for (int u = 0; u < 8; u++)
        #pragma unroll
        for (int v = 0; v < 8; v++) acc[u][v] = 0.f;

    #pragma unroll
    for (int m = 0; m < MIDD; m++) {
        float ai[8], bj[8];
        #pragma unroll
        for (int u = 0; u < 8; u++) { ai[u] = As[m][tiq*8+u]; bj[u] = Bs[m][tj*8+u]; }
        #pragma unroll
        for (int u = 0; u < 8; u++)
            #pragma unroll
            for (int v = 0; v < 8; v++) acc[u][v] += ai[u] * bj[v];
    }

    const float mb = g_mx[b];
    __nv_bfloat16* E = g_E + (size_t)b*NN*NN;
    float zp[8];
    #pragma unroll
    for (int v = 0; v < 8; v++) zp[v] = 0.f;

    #pragma unroll
    for (int u = 0; u < 8; u++) {
        float e[8];
        #pragma unroll
        for (int v = 0; v < 8; v++) {
            e[v] = __expf(acc[u][v] - mb);
            zp[v] += e[v];
        }
        uint4 w;
        w.x = pk_bf2(e[0], e[1]); w.y = pk_bf2(e[2], e[3]);
        w.z = pk_bf2(e[4], e[5]); w.w = pk_bf2(e[6], e[7]);
        *(uint4*)(E + (size_t)(i0 + tiq*8 + u)*NN + j0 + tj*8) = w;
    }
    #pragma unroll
    for (int v = 0; v < 8; v++) atomicAdd(&Zsm[tj*8 + v], zp[v]);
    __syncthreads();
    if (tid < 128) atomicAdd(&g_Zs[b*NN + j0 + tid], Zsm[tid]);
}

// ---------------- K4: CsH[k][j] = (WcX+bc)[k][j] / Z[j]  bf16 -------------------
__global__ void k_c(const float* __restrict__ x,
                    const float* __restrict__ wc, const float* __restrict__ bc)
{
    __shared__ float ws[32*CC];
    const int b  = blockIdx.y;
    const int kc = blockIdx.z;
    for (int i = threadIdx.x; i < 32*CC; i += 256) ws[i] = wc[kc*32*CC + i];
    __syncthreads();

    const int tx = threadIdx.x & 63;
    const int ty = threadIdx.x >> 6;
    const int n0 = blockIdx.x*256 + tx*4;
    const float* Z = &g_Zs[b*NN];
    float iz0 = 1.f/Z[n0], iz1 = 1.f/Z[n0+1], iz2 = 1.f/Z[n0+2], iz3 = 1.f/Z[n0+3];

    const float* xb = x + (size_t)b*CC*NN;
    float a0[8], a1[8], a2[8], a3[8];
    #pragma unroll
    for (int m = 0; m < 8; m++) {
        float bv = bc[kc*32 + ty*8 + m];
        a0[m]=bv; a1[m]=bv; a2[m]=bv; a3[m]=bv;
    }
    for (int c = 0; c < CC; c += 4) {
        float4 x0 = *(const float4*)(xb + (c+0)*NN + n0);
        float4 x1 = *(const float4*)(xb + (c+1)*NN + n0);
        float4 x2 = *(const float4*)(xb + (c+2)*NN + n0);
        float4 x3 = *(const float4*)(xb + (c+3)*NN + n0);
        #pragma unroll
        for (int m = 0; m < 8; m++) {
            float4 w = *(const float4*)&ws[(ty*8+m)*CC + c];
            a0[m] += w.x*x0.x + w.y*x1.x + w.z*x2.x + w.w*x3.x;
            a1[m] += w.x*x0.y + w.y*x1.y + w.z*x2.y + w.w*x3.y;
            a2[m] += w.x*x0.z + w.y*x1.z + w.z*x2.z + w.w*x3.z;
            a3[m] += w.x*x0.w + w.y*x1.w + w.z*x2.w + w.w*x3.w;
        }
    }
    __nv_bfloat16* Cb = g_CsH[b];
    #pragma unroll
    for (int m = 0; m < 8; m++) {
        int k = kc*32 + ty*8 + m;
        uint2 o;
        o.x = pk_bf2(a0[m]*iz0, a1[m]*iz1);
        o.y = pk_bf2(a2[m]*iz2, a3[m]*iz3);
        *(uint2*)(Cb + (size_t)k*NN + n0) = o;
    }
}

// ---------------- K5: bf16 mma: out[i][k] = sum_j E[i][j]*CsH[k][j] ------------
// 512 thr = 16 warps (2 M x 8 N). Block M=128, N=256, K-chunk 64, double-buffered.
#define JC 64
#define EROW 144
#define EBYTES (128*EROW)     // 18432
#define CBYTES (256*EROW)     // 36864
#define BUFB (EBYTES + CBYTES)
#define KO_SMEM (2*BUFB)      // 110592

__global__ void __launch_bounds__(512, 1) k_out_bf16()
{
    extern __shared__ char sm[];
    const uint32_t sb = smem_u32(sm);
    const int tid  = threadIdx.x;
    const int lane = tid & 31;
    const int warp = tid >> 5;
    const int wm   = warp & 1;
    const int wn   = warp >> 1;
    const int b    = blockIdx.y;
    const int i0   = blockIdx.x * 128;
    const int lr   = lane >> 2;
    const int lc   = lane & 3;

    const __nv_bfloat16* E  = g_E + (size_t)b*NN*NN;
    const __nv_bfloat16* Ch = g_CsH[b];

    float acc[4][4][4];
    #pragma unroll
    for (int mf = 0; mf < 4; mf++)
        #pragma unroll
        for (int nf = 0; nf < 4; nf++)
            #pragma unroll
            for (int q = 0; q < 4; q++) acc[mf][nf][q] = 0.f;

    // stage chunk ch into buffer s
    #define ISSUE(ch, s) do {                                                   \
        uint32_t eb = sb + (s)*BUFB, cb = eb + EBYTES;                          \
        int _j0 = (ch)*JC;                                                      \
        _Pragma("unroll")                                                       \
        for (int r = 0; r < 2; r++) {                                           \
            int id = tid + 512*r; int row = id >> 3, q = id & 7;                \
            CP16(eb + row*EROW + q*16,                                          \
                 (const char*)(E + (size_t)(i0+row)*NN + _j0) + q*16);          \
        }                                                                       \
        _Pragma("unroll")                                                       \
        for (int r = 0; r < 4; r++) {                                           \
            int id = tid + 512*r; int row = id >> 3, q = id & 7;                \
            CP16(cb + row*EROW + q*16,                                          \
                 (const char*)(Ch + (size_t)row*NN + _j0) + q*16);              \
        }                                                                       \
        CP_COMMIT();                                                            \
    } while (0)

    ISSUE(0, 0);
    const int NCH = NN / JC;
    for (int ch = 0; ch < NCH; ch++) {
        const int s = ch & 1;
        if (ch + 1 < NCH) { ISSUE(ch+1, s^1); CP_WAIT(1); }
        else              { CP_WAIT(0); }
        __syncthreads();

        const char* eb = sm + s*BUFB;
        const char* cb = eb + EBYTES;
        #pragma unroll
        for (int ks = 0; ks < 4; ks++) {
            const int jb = ks * 16;
            uint32_t afr[4][4], bfr[4][2];
            #pragma unroll
            for (int mf = 0; mf < 4; mf++) {
                const char* a = eb + (wm*64 + mf*16 + lr)*EROW + (jb + 2*lc)*2;
                afr[mf][0] = *(const uint32_t*)(a);
                afr[mf][1] = *(const uint32_t*)(a + 8*EROW);
                afr[mf][2] = *(const uint32_t*)(a + 16);
                afr[mf][3] = *(const uint32_t*)(a + 8*EROW + 16);
            }
            #pragma unroll
            for (int nf = 0; nf < 4; nf++) {
                const char* bq = cb + (wn*32 + nf*8 + lr)*EROW + (jb + 2*lc)*2;
                bfr[nf][0] = *(const uint32_t*)(bq);
                bfr[nf][1] = *(const uint32_t*)(bq + 16);
            }
            #pragma unroll
            for (int mf = 0; mf < 4; mf++)
                #pragma unroll
                for (int nf = 0; nf < 4; nf++)
                    mma_bf16(acc[mf][nf], afr[mf], bfr[nf]);
        }
        __syncthreads();
    }

    float* Ob = g_O[b];
    #pragma unroll
    for (int mf = 0; mf < 4; mf++) {
        int row0 = i0 + wm*64 + mf*16 + lr;
        #pragma unroll
        for (int nf = 0; nf < 4; nf++) {
            int col = wn*32 + nf*8 + 2*lc;
            *(float2*)(Ob + (size_t)row0*CC + col) =
                make_float2(acc[mf][nf][0], acc[mf][nf][1]);
            *(float2*)(Ob + (size_t)(row0+8)*CC + col) =
                make_float2(acc[mf][nf][2], acc[mf][nf][3]);
        }
    }
}

// ---------------- K6: final = Wo(beta*Y + X) + bo -------------------------------
__global__ void k_final(const float* __restrict__ x,
                        const float* __restrict__ wo, const float* __restrict__ bo,
                        const float* __restrict__ beta, float* __restrict__ out)
{
    __shared__ float ws[32*CC];
    const int b  = blockIdx.y;
    const int kc = blockIdx.z;
    for (int i = threadIdx.x; i < 32*CC; i += 256) ws[i] = wo[kc*32*CC + i];
    __syncthreads();

    const int tx = threadIdx.x & 63;
    const int ty = threadIdx.x >> 6;
    const int n0 = blockIdx.x*256 + tx*4;
    const float bt = beta[0];
    const float* xb = x + (size_t)b*CC*NN;
    const float* Yb = g_O[b];

    float a0[8], a1[8], a2[8], a3[8];
    #pragma unroll
    for (int m = 0; m < 8; m++) {
        float bv = bo[kc*32 + ty*8 + m];
        a0[m]=bv; a1[m]=bv; a2[m]=bv; a3[m]=bv;
    }
    for (int c = 0; c < CC; c += 4) {
        float4 v[4];
        #pragma unroll
        for (int cc = 0; cc < 4; cc++) {
            float4 xv = *(const float4*)(xb + (c+cc)*NN + n0);
            float4 yv = *(const float4*)(Yb + (c+cc)*NN + n0);
            v[cc].x = fmaf(bt, yv.x, xv.x);
            v[cc].y = fmaf(bt, yv.y, xv.y);
            v[cc].z = fmaf(bt, yv.z, xv.z);
            v[cc].w = fmaf(bt, yv.w, xv.w);
        }
        #pragma unroll
        for (int m = 0; m < 8; m++) {
            float4 w = *(const float4*)&ws[(ty*8+m)*CC + c];
            a0[m] += w.x*v[0].x + w.y*v[1].x + w.z*v[2].x + w.w*v[3].x;
            a1[m] += w.x*v[0].y + w.y*v[1].y + w.z*v[2].y + w.w*v[3].y;
            a2[m] += w.x*v[0].z + w.y*v[1].z + w.z*v[2].z + w.w*v[3].z;
            a3[m] += w.x*v[0].w + w.y*v[1].w + w.z*v[2].w + w.w*v[3].w;
        }
    }
    #pragma unroll
    for (int m = 0; m < 8; m++) {
        int k = kc*32 + ty*8 + m;
        *(float4*)(out + ((size_t)b*CC + k)*NN + n0) = make_float4(a0[m], a1[m], a2[m], a3[m]);
    }
}

// ---------------- launch --------------------------------------------------------
extern "C" void kernel_launch(void* const* d_in, const int* in_sizes, int n_in,
                              void* d_out, int out_size)
{
    const float* x    = (const float*)d_in[0];
    const float* wa   = (const float*)d_in[1];
    const float* ba   = (const float*)d_in[2];
    const float* wb   = (const float*)d_in[3];
    const float* bb   = (const float*)d_in[4];
    const float* wc   = (const float*)d_in[5];
    const float* bc   = (const float*)d_in[6];
    const float* wo   = (const float*)d_in[7];
    const float* bo   = (const float*)d_in[8];
    const float* beta = (const float*)d_in[9];
    float* out = (float*)d_out;

    cudaFuncSetAttribute(k_out_bf16, cudaFuncAttributeMaxDynamicSharedMemorySize, KO_SMEM);

    k_zero    <<<(BB*NN + 1023)/1024, 1024>>>();
    k_ab      <<<dim3(NN/256, BB, 2),      256>>>(x, wa, ba, wb, bb);
    k_norm    <<<BB, 256>>>();
    k_pt_e    <<<dim3(NN/128, NN/128, BB), 256>>>();
    k_c       <<<dim3(NN/256, BB, CC/32),  256>>>(x, wc, bc);
    k_out_bf16<<<dim3(NN/128, BB), 512, KO_SMEM>>>();
    k_final   <<<dim3(NN/256, BB, CC/32),  256>>>(x, wo, bo, beta, out);
}

// round 5
// speedup vs baseline: 3.6774x; 1.1066x over previous
#include <cuda_runtime.h>
#include <cuda_bf16.h>
#include <math.h>
#include <stdint.h>

#define BB  8
#define CC  256
#define MIDD 32
#define NN  4096

// ---------------- scratch ----------------------------------------------------
__device__ float g_A  [BB][MIDD*NN];
__device__ float g_Bm [BB][MIDD*NN];
__device__ __nv_bfloat16 g_E[(size_t)BB*NN*NN];   // 268 MB, E[i][j] = exp(p-m)
__device__ float g_mx [BB];                       // per-batch softmax upper bound
__device__ float g_Zs [BB*NN];                    // Z[j] (atomic accumulated)
__device__ __nv_bfloat16 g_CsH[BB][CC*NN];        // (WcX+bc)/Z  [k][j] bf16
__device__ float g_O  [BB][NN*CC];                // out [i][k] (== Y[c][n] flat)

__device__ __forceinline__ uint32_t smem_u32(const void* p) {
    uint32_t a;
    asm("{ .reg .u64 t; cvta.to.shared.u64 t, %1; cvt.u32.u64 %0, t; }" : "=r"(a) : "l"(p));
    return a;
}
__device__ __forceinline__ uint32_t pk_bf2(float a, float b) {
    __nv_bfloat162 h = __floats2bfloat162_rn(a, b);
    return *(uint32_t*)&h;
}
__device__ __forceinline__ uint32_t to_tf32(float f) {
    uint32_t u;
    asm("cvt.rna.tf32.f32 %0, %1;" : "=r"(u) : "f"(f));
    return u;
}
#define CP16(dst, src) asm volatile("cp.async.cg.shared.global [%0], [%1], 16;" :: "r"(dst), "l"(src))
#define CP_COMMIT()    asm volatile("cp.async.commit_group;" ::: "memory")
#define CP_WAIT(n)     asm volatile("cp.async.wait_group %0;" :: "n"(n) : "memory")

__device__ __forceinline__ void mma_bf16(float* c, const uint32_t* a, const uint32_t* b) {
    asm volatile(
        "mma.sync.aligned.m16n8k16.row.col.f32.bf16.bf16.f32 "
        "{%0,%1,%2,%3}, {%4,%5,%6,%7}, {%8,%9}, {%0,%1,%2,%3};"
        : "+f"(c[0]), "+f"(c[1]), "+f"(c[2]), "+f"(c[3])
        : "r"(a[0]), "r"(a[1]), "r"(a[2]), "r"(a[3]), "r"(b[0]), "r"(b[1]));
}
__device__ __forceinline__ void mma_tf32(float* c, const uint32_t* a, const uint32_t* b) {
    asm volatile(
        "mma.sync.aligned.m16n8k8.row.col.f32.tf32.tf32.f32 "
        "{%0,%1,%2,%3}, {%4,%5,%6,%7}, {%8,%9}, {%0,%1,%2,%3};"
        : "+f"(c[0]), "+f"(c[1]), "+f"(c[2]), "+f"(c[3])
        : "r"(a[0]), "r"(a[1]), "r"(a[2]), "r"(a[3]), "r"(b[0]), "r"(b[1]));
}

// ---------------- K0: zero Z ---------------------------------------------------
__global__ void k_zero() {
    int i = blockIdx.x*1024 + threadIdx.x;
    if (i < BB*NN) g_Zs[i] = 0.f;
}

// ---------------- K1: A = WaX+ba, B = WbX+bb ----------------------------------
__global__ void k_ab(const float* __restrict__ x,
                     const float* __restrict__ wa, const float* __restrict__ ba,
                     const float* __restrict__ wb, const float* __restrict__ bb)
{
    __shared__ float ws[MIDD*CC];
    __shared__ float bs[MIDD];
    const int b = blockIdx.y;
    const int which = blockIdx.z;
    const float* w    = which ? wb : wa;
    const float* bias = which ? bb : ba;
    float* outp       = which ? g_Bm[b] : g_A[b];

    for (int i = threadIdx.x; i < MIDD*CC; i += 256) ws[i] = w[i];
    if (threadIdx.x < MIDD) bs[threadIdx.x] = bias[threadIdx.x];
    __syncthreads();

    const int n = blockIdx.x*256 + threadIdx.x;
    const float* xb = x + (size_t)b*CC*NN;
    float acc[MIDD];
    #pragma unroll
    for (int m = 0; m < MIDD; m++) acc[m] = bs[m];
    for (int c = 0; c < CC; c++) {
        float xv = xb[c*NN + n];
        #pragma unroll
        for (int m = 0; m < MIDD; m++) acc[m] += ws[m*CC + c] * xv;
    }
    #pragma unroll
    for (int m = 0; m < MIDD; m++) outp[m*NN + n] = acc[m];
}

// ---------------- K2: per-batch bound m = max||a|| * max||b|| -------------------
__global__ void k_norm() {
    const int b = blockIdx.x;
    const int t = threadIdx.x;
    const float* A  = g_A [b];
    const float* Bm = g_Bm[b];
    float ma = 0.f, mb = 0.f;
    for (int i = t; i < NN; i += 256) {
        float sa = 0.f, sb = 0.f;
        #pragma unroll
        for (int m = 0; m < MIDD; m++) {
            float av = A [m*NN + i]; sa += av*av;
            float bv = Bm[m*NN + i]; sb += bv*bv;
        }
        ma = fmaxf(ma, sa); mb = fmaxf(mb, sb);
    }
    __shared__ float ra[256], rb[256];
    ra[t] = ma; rb[t] = mb; __syncthreads();
    for (int s = 128; s > 0; s >>= 1) {
        if (t < s) { ra[t] = fmaxf(ra[t], ra[t+s]); rb[t] = fmaxf(rb[t], rb[t+s]); }
        __syncthreads();
    }
    if (t == 0) g_mx[b] = sqrtf(ra[0]) * sqrtf(rb[0]);
}

// ---------------- K3: tf32 mma logits -> exp -> E bf16, Z[j] accumulation ------
// Block: 128 i x 128 j, K = MID = 32 (4 k-steps of 8). 256 thr = 8 warps (2i x 4j).
#define APAD 36
__global__ void __launch_bounds__(256, 2) k_pt_e()
{
    __shared__ float As[128][APAD];   // [i][m], tf32-rounded
    __shared__ float Bs[128][APAD];   // [j][m], tf32-rounded
    __shared__ float Zsm[128];

    const int b  = blockIdx.z;
    const int i0 = blockIdx.y * 128;
    const int j0 = blockIdx.x * 128;
    const float* A  = g_A [b];
    const float* Bm = g_Bm[b];
    const int tid  = threadIdx.x;
    const int lane = tid & 31;
    const int warp = tid >> 5;
    const int wm   = warp & 1;        // i half
    const int wn   = warp >> 1;       // j quarter
    const int lr   = lane >> 2;
    const int lc   = lane & 3;

    for (int idx = tid; idx < 128*MIDD; idx += 256) {
        int m = idx >> 7, t = idx & 127;
        As[t][m] = __uint_as_float(to_tf32(A [m*NN + i0 + t]));
        Bs[t][m] = __uint_as_float(to_tf32(Bm[m*NN + j0 + t]));
    }
    if (tid < 128) Zsm[tid] = 0.f;
    __syncthreads();

    float acc[4][4][4];
    #pragma unroll
    for (int mf = 0; mf < 4; mf++)
        #pragma unroll
        for (int nf = 0; nf < 4; nf++)
            #pragma unroll
            for (int q = 0; q < 4; q++) acc[mf][nf][q] = 0.f;

    #pragma unroll
    for (int ks = 0; ks < 4; ks++) {
        const int mb8 = ks * 8;
        uint32_t afr[4][4], bfr[4][2];
        #pragma unroll
        for (int mf = 0; mf < 4; mf++) {
            const float* ap = &As[wm*64 + mf*16 + lr][mb8 + lc];
            afr[mf][0] = __float_as_uint(ap[0]);
            afr[mf][1] = __float_as_uint(ap[8*APAD]);
            afr[mf][2] = __float_as_uint(ap[4]);
            afr[mf][3] = __float_as_uint(ap[8*APAD + 4]);
        }
        #pragma unroll
        for (int nf = 0; nf < 4; nf++) {
            const float* bp = &Bs[wn*32 + nf*8 + lr][mb8 + lc];
            bfr[nf][0] = __float_as_uint(bp[0]);
            bfr[nf][1] = __float_as_uint(bp[4]);
        }
        #pragma unroll
        for (int mf = 0; mf < 4; mf++)
            #pragma unroll
            for (int nf = 0; nf < 4; nf++)
                mma_tf32(acc[mf][nf], afr[mf], bfr[nf]);
    }

    // epilogue: exp on fragments, pack bf16x2, column sums for Z
    const float mbv = g_mx[b];
    __nv_bfloat16* E = g_E + (size_t)b*NN*NN;
    float z0[4], z1[4];
    #pragma unroll
    for (int nf = 0; nf < 4; nf++) { z0[nf] = 0.f; z1[nf] = 0.f; }

    #pragma unroll
    for (int mf = 0; mf < 4; mf++) {
        const int row = i0 + wm*64 + mf*16 + lr;
        #pragma unroll
        for (int nf = 0; nf < 4; nf++) {
            const int col = j0 + wn*32 + nf*8 + 2*lc;
            float e0 = __expf(acc[mf][nf][0] - mbv);
            float e1 = __expf(acc[mf][nf][1] - mbv);
            float e2 = __expf(acc[mf][nf][2] - mbv);
            float e3 = __expf(acc[mf][nf][3] - mbv);
            *(uint32_t*)(E + (size_t)row*NN + col)     = pk_bf2(e0, e1);
            *(uint32_t*)(E + (size_t)(row+8)*NN + col) = pk_bf2(e2, e3);
            z0[nf] += e0 + e2;
            z1[nf] += e1 + e3;
        }
    }
    // reduce over lr lanes (lane = lr*4 + lc): xor masks 4,8,16
    #pragma unroll
    for (int nf = 0; nf < 4; nf++) {
        float s0 = z0[nf], s1 = z1[nf];
        #pragma unroll
        for (int msk = 4; msk <= 16; msk <<= 1) {
            s0 += __shfl_xor_sync(0xFFFFFFFF, s0, msk);
            s1 += __shfl_xor_sync(0xFFFFFFFF, s1, msk);
        }
        if (lr == 0) {
            atomicAdd(&Zsm[wn*32 + nf*8 + 2*lc],     s0);
            atomicAdd(&Zsm[wn*32 + nf*8 + 2*lc + 1], s1);
        }
    }
    __syncthreads();
    if (tid < 128) atomicAdd(&g_Zs[b*NN + j0 + tid], Zsm[tid]);
}

// ---------------- K4: CsH[k][j] = (WcX+bc)[k][j] / Z[j]  bf16 -------------------
__global__ void k_c(const float* __restrict__ x,
                    const float* __restrict__ wc, const float* __restrict__ bc)
{
    __shared__ float ws[32*CC];
    const int b  = blockIdx.y;
    const int kc = blockIdx.z;
    for (int i = threadIdx.x; i < 32*CC; i += 256) ws[i] = wc[kc*32*CC + i];
    __syncthreads();

    const int tx = threadIdx.x & 63;
    const int ty = threadIdx.x >> 6;
    const int n0 = blockIdx.x*256 + tx*4;
    const float* Z = &g_Zs[b*NN];
    float iz0 = 1.f/Z[n0], iz1 = 1.f/Z[n0+1], iz2 = 1.f/Z[n0+2], iz3 = 1.f/Z[n0+3];

    const float* xb = x + (size_t)b*CC*NN;
    float a0[8], a1[8], a2[8], a3[8];
    #pragma unroll
    for (int m = 0; m < 8; m++) {
        float bv = bc[kc*32 + ty*8 + m];
        a0[m]=bv; a1[m]=bv; a2[m]=bv; a3[m]=bv;
    }
    for (int c = 0; c < CC; c += 4) {
        float4 x0 = *(const float4*)(xb + (c+0)*NN + n0);
        float4 x1 = *(const float4*)(xb + (c+1)*NN + n0);
        float4 x2 = *(const float4*)(xb + (c+2)*NN + n0);
        float4 x3 = *(const float4*)(xb + (c+3)*NN + n0);
        #pragma unroll
        for (int m = 0; m < 8; m++) {
            float4 w = *(const float4*)&ws[(ty*8+m)*CC + c];
            a0[m] += w.x*x0.x + w.y*x1.x + w.z*x2.x + w.w*x3.x;
            a1[m] += w.x*x0.y + w.y*x1.y + w.z*x2.y + w.w*x3.y;
            a2[m] += w.x*x0.z + w.y*x1.z + w.z*x2.z + w.w*x3.z;
            a3[m] += w.x*x0.w + w.y*x1.w + w.z*x2.w + w.w*x3.w;
        }
    }
    __nv_bfloat16* Cb = g_CsH[b];
    #pragma unroll
    for (int m = 0; m < 8; m++) {
        int k = kc*32 + ty*8 + m;
        uint2 o;
        o.x = pk_bf2(a0[m]*iz0, a1[m]*iz1);
        o.y = pk_bf2(a2[m]*iz2, a3[m]*iz3);
        *(uint2*)(Cb + (size_t)k*NN + n0) = o;
    }
}

// ---------------- K5: bf16 mma: out[i][k] = sum_j E[i][j]*CsH[k][j] ------------
#define JC 64
#define EROW 144
#define EBYTES (128*EROW)
#define CBYTES (256*EROW)
#define BUFB (EBYTES + CBYTES)
#define KO_SMEM (2*BUFB)

__global__ void __launch_bounds__(512, 1) k_out_bf16()
{
    extern __shared__ char sm[];
    const uint32_t sb = smem_u32(sm);
    const int tid  = threadIdx.x;
    const int lane = tid & 31;
    const int warp = tid >> 5;
    const int wm   = warp & 1;
    const int wn   = warp >> 1;
    const int b    = blockIdx.y;
    const int i0   = blockIdx.x * 128;
    const int lr   = lane >> 2;
    const int lc   = lane & 3;

    const __nv_bfloat16* E  = g_E + (size_t)b*NN*NN;
    const __nv_bfloat16* Ch = g_CsH[b];

    float acc[4][4][4];
    #pragma unroll
    for (int mf = 0; mf < 4; mf++)
        #pragma unroll
        for (int nf = 0; nf < 4; nf++)
            #pragma unroll
            for (int q = 0; q < 4; q++) acc[mf][nf][q] = 0.f;

    #define ISSUE(ch, s) do {                                                   \
        uint32_t eb = sb + (s)*BUFB, cb = eb + EBYTES;                          \
        int _j0 = (ch)*JC;                                                      \
        _Pragma("unroll")                                                       \
        for (int r = 0; r < 2; r++) {                                           \
            int id = tid + 512*r; int row = id >> 3, q = id & 7;                \
            CP16(eb + row*EROW + q*16,                                          \
                 (const char*)(E + (size_t)(i0+row)*NN + _j0) + q*16);          \
        }                                                                       \
        _Pragma("unroll")                                                       \
        for (int r = 0; r < 4; r++) {                                           \
            int id = tid + 512*r; int row = id >> 3, q = id & 7;                \
            CP16(cb + row*EROW + q*16,                                          \
                 (const char*)(Ch + (size_t)row*NN + _j0) + q*16);              \
        }                                                                       \
        CP_COMMIT();                                                            \
    } while (0)

    ISSUE(0, 0);
    const int NCH = NN / JC;
    for (int ch = 0; ch < NCH; ch++) {
        const int s = ch & 1;
        if (ch + 1 < NCH) { ISSUE(ch+1, s^1); CP_WAIT(1); }
        else              { CP_WAIT(0); }
        __syncthreads();

        const char* eb = sm + s*BUFB;
        const char* cb = eb + EBYTES;
        #pragma unroll
        for (int ks = 0; ks < 4; ks++) {
            const int jb = ks * 16;
            uint32_t afr[4][4], bfr[4][2];
            #pragma unroll
            for (int mf = 0; mf < 4; mf++) {
                const char* a = eb + (wm*64 + mf*16 + lr)*EROW + (jb + 2*lc)*2;
                afr[mf][0] = *(const uint32_t*)(a);
                afr[mf][1] = *(const uint32_t*)(a + 8*EROW);
                afr[mf][2] = *(const uint32_t*)(a + 16);
                afr[mf][3] = *(const uint32_t*)(a + 8*EROW + 16);
            }
            #pragma unroll
            for (int nf = 0; nf < 4; nf++) {
                const char* bq = cb + (wn*32 + nf*8 + lr)*EROW + (jb + 2*lc)*2;
                bfr[nf][0] = *(const uint32_t*)(bq);
                bfr[nf][1] = *(const uint32_t*)(bq + 16);
            }
            #pragma unroll
            for (int mf = 0; mf < 4; mf++)
                #pragma unroll
                for (int nf = 0; nf < 4; nf++)
                    mma_bf16(acc[mf][nf], afr[mf], bfr[nf]);
        }
        __syncthreads();
    }

    float* Ob = g_O[b];
    #pragma unroll
    for (int mf = 0; mf < 4; mf++) {
        int row0 = i0 + wm*64 + mf*16 + lr;
        #pragma unroll
        for (int nf = 0; nf < 4; nf++) {
            int col = wn*32 + nf*8 + 2*lc;
            *(float2*)(Ob + (size_t)row0*CC + col) =
                make_float2(acc[mf][nf][0], acc[mf][nf][1]);
            *(float2*)(Ob + (size_t)(row0+8)*CC + col) =
                make_float2(acc[mf][nf][2], acc[mf][nf][3]);
        }
    }
}

// ---------------- K6: final = Wo(beta*Y + X) + bo -------------------------------
__global__ void k_final(const float* __restrict__ x,
                        const float* __restrict__ wo, const float* __restrict__ bo,
                        const float* __restrict__ beta, float* __restrict__ out)
{
    __shared__ float ws[32*CC];
    const int b  = blockIdx.y;
    const int kc = blockIdx.z;
    for (int i = threadIdx.x; i < 32*CC; i += 256) ws[i] = wo[kc*32*CC + i];
    __syncthreads();

    const int tx = threadIdx.x & 63;
    const int ty = threadIdx.x >> 6;
    const int n0 = blockIdx.x*256 + tx*4;
    const float bt = beta[0];
    const float* xb = x + (size_t)b*CC*NN;
    const float* Yb = g_O[b];

    float a0[8], a1[8], a2[8], a3[8];
    #pragma unroll
    for (int m = 0; m < 8; m++) {
        float bv = bo[kc*32 + ty*8 + m];
        a0[m]=bv; a1[m]=bv; a2[m]=bv; a3[m]=bv;
    }
    for (int c = 0; c < CC; c += 4) {
        float4 v[4];
        #pragma unroll
        for (int cc = 0; cc < 4; cc++) {
            float4 xv = *(const float4*)(xb + (c+cc)*NN + n0);
            float4 yv = *(const float4*)(Yb + (c+cc)*NN + n0);
            v[cc].x = fmaf(bt, yv.x, xv.x);
            v[cc].y = fmaf(bt, yv.y, xv.y);
            v[cc].z = fmaf(bt, yv.z, xv.z);
            v[cc].w = fmaf(bt, yv.w, xv.w);
        }
        #pragma unroll
        for (int m = 0; m < 8; m++) {
            float4 w = *(const float4*)&ws[(ty*8+m)*CC + c];
            a0[m] += w.x*v[0].x + w.y*v[1].x + w.z*v[2].x + w.w*v[3].x;
            a1[m] += w.x*v[0].y + w.y*v[1].y + w.z*v[2].y + w.w*v[3].y;
            a2[m] += w.x*v[0].z + w.y*v[1].z + w.z*v[2].z + w.w*v[3].z;
            a3[m] += w.x*v[0].w + w.y*v[1].w + w.z*v[2].w + w.w*v[3].w;
        }
    }
    #pragma unroll
    for (int m = 0; m < 8; m++) {
        int k = kc*32 + ty*8 + m;
        *(float4*)(out + ((size_t)b*CC + k)*NN + n0) = make_float4(a0[m], a1[m], a2[m], a3[m]);
    }
}

// ---------------- launch --------------------------------------------------------
extern "C" void kernel_launch(void* const* d_in, const int* in_sizes, int n_in,
                              void* d_out, int out_size)
{
    const float* x    = (const float*)d_in[0];
    const float* wa   = (const float*)d_in[1];
    const float* ba   = (const float*)d_in[2];
    const float* wb   = (const float*)d_in[3];
    const float* bb   = (const float*)d_in[4];
    const float* wc   = (const float*)d_in[5];
    const float* bc   = (const float*)d_in[6];
    const float* wo   = (const float*)d_in[7];
    const float* bo   = (const float*)d_in[8];
    const float* beta = (const float*)d_in[9];
    float* out = (float*)d_out;

    cudaFuncSetAttribute(k_out_bf16, cudaFuncAttributeMaxDynamicSharedMemorySize, KO_SMEM);

    k_zero    <<<(BB*NN + 1023)/1024, 1024>>>();
    k_ab      <<<dim3(NN/256, BB, 2),      256>>>(x, wa, ba, wb, bb);
    k_norm    <<<BB, 256>>>();
    k_pt_e    <<<dim3(NN/128, NN/128, BB), 256>>>();
    k_c       <<<dim3(NN/256, BB, CC/32),  256>>>(x, wc, bc);
    k_out_bf16<<<dim3(NN/128, BB), 512, KO_SMEM>>>();
    k_final   <<<dim3(NN/256, BB, CC/32),  256>>>(x, wo, bo, beta, out);
}

// round 6
// speedup vs baseline: 4.9669x; 1.3507x over previous
#include <cuda_runtime.h>
#include <cuda_bf16.h>
#include <math.h>
#include <stdint.h>

#define BB  8
#define CC  256
#define MIDD 32
#define NN  4096

// ---------------- scratch ----------------------------------------------------
__device__ float g_A  [BB][MIDD*NN];
__device__ float g_Bm [BB][MIDD*NN];
__device__ __nv_bfloat16 g_E[(size_t)BB*NN*NN];   // 268 MB, E[i][j] = exp(p-m)
__device__ float g_mx [BB];
__device__ float g_Zs [BB*NN];
__device__ __nv_bfloat16 g_CsH[BB][CC*NN];        // (WcX+bc)/Z  [k][j] bf16
__device__ float g_O  [BB][NN*CC];                // out [i][k] (== Y[c][n] flat)

__device__ __forceinline__ uint32_t smem_u32(const void* p) {
    uint32_t a;
    asm("{ .reg .u64 t; cvta.to.shared.u64 t, %1; cvt.u32.u64 %0, t; }" : "=r"(a) : "l"(p));
    return a;
}
__device__ __forceinline__ uint32_t pk_bf2(float a, float b) {
    __nv_bfloat162 h = __floats2bfloat162_rn(a, b);
    return *(uint32_t*)&h;
}
__device__ __forceinline__ float to_tf32f(float f) {
    uint32_t u;
    asm("cvt.rna.tf32.f32 %0, %1;" : "=r"(u) : "f"(f));
    return __uint_as_float(u);
}
#define CP16(dst, src) asm volatile("cp.async.cg.shared.global [%0], [%1], 16;" :: "r"(dst), "l"(src))
#define CP_COMMIT()    asm volatile("cp.async.commit_group;" ::: "memory")
#define CP_WAIT(n)     asm volatile("cp.async.wait_group %0;" :: "n"(n) : "memory")

__device__ __forceinline__ void mma_bf16(float* c, const uint32_t* a, const uint32_t* b) {
    asm volatile(
        "mma.sync.aligned.m16n8k16.row.col.f32.bf16.bf16.f32 "
        "{%0,%1,%2,%3}, {%4,%5,%6,%7}, {%8,%9}, {%0,%1,%2,%3};"
        : "+f"(c[0]), "+f"(c[1]), "+f"(c[2]), "+f"(c[3])
        : "r"(a[0]), "r"(a[1]), "r"(a[2]), "r"(a[3]), "r"(b[0]), "r"(b[1]));
}
__device__ __forceinline__ void mma_tf32(float* c, const uint32_t* a, const uint32_t* b) {
    asm volatile(
        "mma.sync.aligned.m16n8k8.row.col.f32.tf32.tf32.f32 "
        "{%0,%1,%2,%3}, {%4,%5,%6,%7}, {%8,%9}, {%0,%1,%2,%3};"
        : "+f"(c[0]), "+f"(c[1]), "+f"(c[2]), "+f"(c[3])
        : "r"(a[0]), "r"(a[1]), "r"(a[2]), "r"(a[3]), "r"(b[0]), "r"(b[1]));
}

// ---------------- K0: zero Z ---------------------------------------------------
__global__ void k_zero() {
    int i = blockIdx.x*1024 + threadIdx.x;
    if (i < BB*NN) g_Zs[i] = 0.f;
}

// ---------------- K1: A = WaX+ba, B = WbX+bb ----------------------------------
__global__ void k_ab(const float* __restrict__ x,
                     const float* __restrict__ wa, const float* __restrict__ ba,
                     const float* __restrict__ wb, const float* __restrict__ bb)
{
    __shared__ float ws[MIDD*CC];
    __shared__ float bs[MIDD];
    const int b = blockIdx.y;
    const int which = blockIdx.z;
    const float* w    = which ? wb : wa;
    const float* bias = which ? bb : ba;
    float* outp       = which ? g_Bm[b] : g_A[b];

    for (int i = threadIdx.x; i < MIDD*CC; i += 256) ws[i] = w[i];
    if (threadIdx.x < MIDD) bs[threadIdx.x] = bias[threadIdx.x];
    __syncthreads();

    const int n = blockIdx.x*256 + threadIdx.x;
    const float* xb = x + (size_t)b*CC*NN;
    float acc[MIDD];
    #pragma unroll
    for (int m = 0; m < MIDD; m++) acc[m] = bs[m];
    for (int c = 0; c < CC; c++) {
        float xv = xb[c*NN + n];
        #pragma unroll
        for (int m = 0; m < MIDD; m++) acc[m] += ws[m*CC + c] * xv;
    }
    #pragma unroll
    for (int m = 0; m < MIDD; m++) outp[m*NN + n] = acc[m];
}

// ---------------- K2: per-batch bound m = max||a|| * max||b|| -------------------
__global__ void k_norm() {
    const int b = blockIdx.x;
    const int t = threadIdx.x;
    const float* A  = g_A [b];
    const float* Bm = g_Bm[b];
    float ma = 0.f, mb = 0.f;
    for (int i = t; i < NN; i += 256) {
        float sa = 0.f, sb = 0.f;
        #pragma unroll
        for (int m = 0; m < MIDD; m++) {
            float av = A [m*NN + i]; sa += av*av;
            float bv = Bm[m*NN + i]; sb += bv*bv;
        }
        ma = fmaxf(ma, sa); mb = fmaxf(mb, sb);
    }
    __shared__ float ra[256], rb[256];
    ra[t] = ma; rb[t] = mb; __syncthreads();
    for (int s = 128; s > 0; s >>= 1) {
        if (t < s) { ra[t] = fmaxf(ra[t], ra[t+s]); rb[t] = fmaxf(rb[t], rb[t+s]); }
        __syncthreads();
    }
    if (t == 0) g_mx[b] = sqrtf(ra[0]) * sqrtf(rb[0]);
}

// ---------------- K3: tf32 mma logits -> exp -> E bf16 (coalesced), Z ----------
// dyn smem layout (floats): As[128*36] | Bs[128*36] | Zsm[128] | Et[128*68 u32]
#define APAD 36
#define PTE_SMEM ((2*128*36 + 128 + 128*68) * 4)   // 72192 B

__global__ void __launch_bounds__(256, 2) k_pt_e()
{
    extern __shared__ float smf[];
    float* As  = smf;
    float* Bs  = smf + 128*APAD;
    float* Zsm = smf + 2*128*APAD;
    uint32_t* Et = (uint32_t*)(smf + 2*128*APAD + 128);   // [128][68]

    const int b  = blockIdx.z;
    const int i0 = blockIdx.y * 128;
    const int j0 = blockIdx.x * 128;
    const float* A  = g_A [b];
    const float* Bm = g_Bm[b];
    const int tid  = threadIdx.x;
    const int lane = tid & 31;
    const int warp = tid >> 5;
    const int wm   = warp & 1;
    const int wn   = warp >> 1;
    const int lr   = lane >> 2;
    const int lc   = lane & 3;

    for (int idx = tid; idx < 128*MIDD; idx += 256) {
        int m = idx >> 7, t = idx & 127;
        As[t*APAD + m] = to_tf32f(A [m*NN + i0 + t]);
        Bs[t*APAD + m] = to_tf32f(Bm[m*NN + j0 + t]);
    }
    if (tid < 128) Zsm[tid] = 0.f;
    __syncthreads();

    float acc[4][4][4];
    #pragma unroll
    for (int mf = 0; mf < 4; mf++)
        #pragma unroll
        for (int nf = 0; nf < 4; nf++)
            #pragma unroll
            for (int q = 0; q < 4; q++) acc[mf][nf][q] = 0.f;

    #pragma unroll
    for (int ks = 0; ks < 4; ks++) {
        const int mb8 = ks * 8;
        uint32_t afr[4][4], bfr[4][2];
        #pragma unroll
        for (int mf = 0; mf < 4; mf++) {
            const float* ap = &As[(wm*64 + mf*16 + lr)*APAD + mb8 + lc];
            afr[mf][0] = __float_as_uint(ap[0]);
            afr[mf][1] = __float_as_uint(ap[8*APAD]);
            afr[mf][2] = __float_as_uint(ap[4]);
            afr[mf][3] = __float_as_uint(ap[8*APAD + 4]);
        }
        #pragma unroll
        for (int nf = 0; nf < 4; nf++) {
            const float* bp = &Bs[(wn*32 + nf*8 + lr)*APAD + mb8 + lc];
            bfr[nf][0] = __float_as_uint(bp[0]);
            bfr[nf][1] = __float_as_uint(bp[4]);
        }
        #pragma unroll
        for (int mf = 0; mf < 4; mf++)
            #pragma unroll
            for (int nf = 0; nf < 4; nf++)
                mma_tf32(acc[mf][nf], afr[mf], bfr[nf]);
    }

    // exp on fragments -> smem tile (conflict-free) + Z partials
    const float mbv = g_mx[b];
    float z0[4], z1[4];
    #pragma unroll
    for (int nf = 0; nf < 4; nf++) { z0[nf] = 0.f; z1[nf] = 0.f; }

    #pragma unroll
    for (int mf = 0; mf < 4; mf++) {
        const int row = wm*64 + mf*16 + lr;
        #pragma unroll
        for (int nf = 0; nf < 4; nf++) {
            const int colu = wn*16 + nf*4 + lc;
            float e0 = __expf(acc[mf][nf][0] - mbv);
            float e1 = __expf(acc[mf][nf][1] - mbv);
            float e2 = __expf(acc[mf][nf][2] - mbv);
            float e3 = __expf(acc[mf][nf][3] - mbv);
            Et[row*68 + colu]     = pk_bf2(e0, e1);
            Et[(row+8)*68 + colu] = pk_bf2(e2, e3);
            z0[nf] += e0 + e2;
            z1[nf] += e1 + e3;
        }
    }
    #pragma unroll
    for (int nf = 0; nf < 4; nf++) {
        float s0 = z0[nf], s1 = z1[nf];
        #pragma unroll
        for (int msk = 4; msk <= 16; msk <<= 1) {
            s0 += __shfl_xor_sync(0xFFFFFFFF, s0, msk);
            s1 += __shfl_xor_sync(0xFFFFFFFF, s1, msk);
        }
        if (lr == 0) {
            atomicAdd(&Zsm[wn*32 + nf*8 + 2*lc],     s0);
            atomicAdd(&Zsm[wn*32 + nf*8 + 2*lc + 1], s1);
        }
    }
    __syncthreads();

    // coalesced E store: 256B per row
    __nv_bfloat16* E = g_E + (size_t)b*NN*NN;
    #pragma unroll
    for (int r = 0; r < 8; r++) {
        int idx = tid + 256*r;
        int row = idx >> 4, q = idx & 15;
        uint4 v = *(uint4*)&Et[row*68 + q*4];
        *(uint4*)(E + (size_t)(i0 + row)*NN + j0 + q*8) = v;
    }
    if (tid < 128) atomicAdd(&g_Zs[b*NN + j0 + tid], Zsm[tid]);
}

// ---------------- K4: bf16 mma conv: CsH[k][n] = (Wc X + bc)[k][n] / Z[n] -------
// Block: M=128 (k half), N=128 (n). 256 thr = 8 warps (2M x 4N), warp 64x32.
#define KCPAD 40
__global__ void __launch_bounds__(256, 2) k_c_mma(
    const float* __restrict__ x, const float* __restrict__ wc,
    const float* __restrict__ bc)
{
    __shared__ __nv_bfloat16 Wt[2][128*KCPAD];
    __shared__ __nv_bfloat16 Xt[2][128*KCPAD];

    const int tid  = threadIdx.x;
    const int lane = tid & 31;
    const int warp = tid >> 5;
    const int wm   = warp & 1;
    const int wn   = warp >> 1;
    const int lr   = lane >> 2;
    const int lc   = lane & 3;
    const int n0   = blockIdx.x * 128;
    const int b    = blockIdx.y;
    const int kz   = blockIdx.z;
    const float* xb = x + (size_t)b*CC*NN;

    float acc[4][4][4];
    #pragma unroll
    for (int mf = 0; mf < 4; mf++)
        #pragma unroll
        for (int nf = 0; nf < 4; nf++)
            #pragma unroll
            for (int q = 0; q < 4; q++) acc[mf][nf][q] = 0.f;

    const int xt = tid & 127, xch = tid >> 7;

    #define STAGE_C(s, c0) do {                                                 \
        _Pragma("unroll")                                                       \
        for (int r = 0; r < 8; r++) {                                           \
            int idx = tid + 256*r;                                              \
            int k = idx >> 4, cp = idx & 15;                                    \
            float2 w2 = *(const float2*)(wc + (kz*128 + k)*CC + (c0) + cp*2);   \
            *(uint32_t*)&Wt[s][k*KCPAD + cp*2] = pk_bf2(w2.x, w2.y);            \
        }                                                                       \
        _Pragma("unroll")                                                       \
        for (int r = 0; r < 16; r++) {                                          \
            int c = xch*16 + r;                                                 \
            Xt[s][xt*KCPAD + c] =                                               \
                __float2bfloat16(xb[(size_t)((c0) + c)*NN + n0 + xt]);          \
        }                                                                       \
    } while (0)

    STAGE_C(0, 0);
    __syncthreads();

    for (int ch = 0; ch < 8; ch++) {
        const int s = ch & 1;
        if (ch + 1 < 8) STAGE_C(s^1, (ch+1)*32);

        #pragma unroll
        for (int ks = 0; ks < 2; ks++) {
            const int jb = ks * 16;
            uint32_t afr[4][4], bfr[4][2];
            #pragma unroll
            for (int mf = 0; mf < 4; mf++) {
                const __nv_bfloat16* ap = &Wt[s][(wm*64 + mf*16 + lr)*KCPAD + jb + 2*lc];
                afr[mf][0] = *(const uint32_t*)(ap);
                afr[mf][1] = *(const uint32_t*)(ap + 8*KCPAD);
                afr[mf][2] = *(const uint32_t*)(ap + 8);
                afr[mf][3] = *(const uint32_t*)(ap + 8*KCPAD + 8);
            }
            #pragma unroll
            for (int nf = 0; nf < 4; nf++) {
                const __nv_bfloat16* bp = &Xt[s][(wn*32 + nf*8 + lr)*KCPAD + jb + 2*lc];
                bfr[nf][0] = *(const uint32_t*)(bp);
                bfr[nf][1] = *(const uint32_t*)(bp + 8);
            }
            #pragma unroll
            for (int mf = 0; mf < 4; mf++)
                #pragma unroll
                for (int nf = 0; nf < 4; nf++)
                    mma_bf16(acc[mf][nf], afr[mf], bfr[nf]);
        }
        __syncthreads();
    }

    const float* Zb = &g_Zs[b*NN];
    float iz0[4], iz1[4];
    #pragma unroll
    for (int nf = 0; nf < 4; nf++) {
        int col = n0 + wn*32 + nf*8 + 2*lc;
        iz0[nf] = 1.f / Zb[col];
        iz1[nf] = 1.f / Zb[col+1];
    }
    __nv_bfloat16* Cb = g_CsH[b];
    #pragma unroll
    for (int mf = 0; mf < 4; mf++) {
        int krow = kz*128 + wm*64 + mf*16 + lr;
        float bc0 = __ldg(bc + krow), bc8 = __ldg(bc + krow + 8);
        #pragma unroll
        for (int nf = 0; nf < 4; nf++) {
            int col = n0 + wn*32 + nf*8 + 2*lc;
            *(uint32_t*)(Cb + (size_t)krow*NN + col) =
                pk_bf2((acc[mf][nf][0] + bc0)*iz0[nf], (acc[mf][nf][1] + bc0)*iz1[nf]);
            *(uint32_t*)(Cb + (size_t)(krow+8)*NN + col) =
                pk_bf2((acc[mf][nf][2] + bc8)*iz0[nf], (acc[mf][nf][3] + bc8)*iz1[nf]);
        }
    }
}

// ---------------- K5: bf16 mma: out[i][k] = sum_j E[i][j]*CsH[k][j] ------------
#define JC 64
#define EROW 144
#define EBYTES (128*EROW)
#define CBYTES (256*EROW)
#define BUFB (EBYTES + CBYTES)
#define KO_SMEM (2*BUFB)

__global__ void __launch_bounds__(512, 1) k_out_bf16()
{
    extern __shared__ char sm[];
    const uint32_t sb = smem_u32(sm);
    const int tid  = threadIdx.x;
    const int lane = tid & 31;
    const int warp = tid >> 5;
    const int wm   = warp & 1;
    const int wn   = warp >> 1;
    const int b    = blockIdx.y;
    const int i0   = blockIdx.x * 128;
    const int lr   = lane >> 2;
    const int lc   = lane & 3;

    const __nv_bfloat16* E  = g_E + (size_t)b*NN*NN;
    const __nv_bfloat16* Ch = g_CsH[b];

    float acc[4][4][4];
    #pragma unroll
    for (int mf = 0; mf < 4; mf++)
        #pragma unroll
        for (int nf = 0; nf < 4; nf++)
            #pragma unroll
            for (int q = 0; q < 4; q++) acc[mf][nf][q] = 0.f;

    #define ISSUE(ch, s) do {                                                   \
        uint32_t eb = sb + (s)*BUFB, cb = eb + EBYTES;                          \
        int _j0 = (ch)*JC;                                                      \
        _Pragma("unroll")                                                       \
        for (int r = 0; r < 2; r++) {                                           \
            int id = tid + 512*r; int row = id >> 3, q = id & 7;                \
            CP16(eb + row*EROW + q*16,                                          \
                 (const char*)(E + (size_t)(i0+row)*NN + _j0) + q*16);          \
        }                                                                       \
        _Pragma("unroll")                                                       \
        for (int r = 0; r < 4; r++) {                                           \
            int id = tid + 512*r; int row = id >> 3, q = id & 7;                \
            CP16(cb + row*EROW + q*16,                                          \
                 (const char*)(Ch + (size_t)row*NN + _j0) + q*16);              \
        }                                                                       \
        CP_COMMIT();                                                            \
    } while (0)

    ISSUE(0, 0);
    const int NCH = NN / JC;
    for (int ch = 0; ch < NCH; ch++) {
        const int s = ch & 1;
        if (ch + 1 < NCH) { ISSUE(ch+1, s^1); CP_WAIT(1); }
        else              { CP_WAIT(0); }
        __syncthreads();

        const char* eb = sm + s*BUFB;
        const char* cb = eb + EBYTES;
        #pragma unroll
        for (int ks = 0; ks < 4; ks++) {
            const int jb = ks * 16;
            uint32_t afr[4][4], bfr[4][2];
            #pragma unroll
            for (int mf = 0; mf < 4; mf++) {
                const char* a = eb + (wm*64 + mf*16 + lr)*EROW + (jb + 2*lc)*2;
                afr[mf][0] = *(const uint32_t*)(a);
                afr[mf][1] = *(const uint32_t*)(a + 8*EROW);
                afr[mf][2] = *(const uint32_t*)(a + 16);
                afr[mf][3] = *(const uint32_t*)(a + 8*EROW + 16);
            }
            #pragma unroll
            for (int nf = 0; nf < 4; nf++) {
                const char* bq = cb + (wn*32 + nf*8 + lr)*EROW + (jb + 2*lc)*2;
                bfr[nf][0] = *(const uint32_t*)(bq);
                bfr[nf][1] = *(const uint32_t*)(bq + 16);
            }
            #pragma unroll
            for (int mf = 0; mf < 4; mf++)
                #pragma unroll
                for (int nf = 0; nf < 4; nf++)
                    mma_bf16(acc[mf][nf], afr[mf], bfr[nf]);
        }
        __syncthreads();
    }

    float* Ob = g_O[b];
    #pragma unroll
    for (int mf = 0; mf < 4; mf++) {
        int row0 = i0 + wm*64 + mf*16 + lr;
        #pragma unroll
        for (int nf = 0; nf < 4; nf++) {
            int col = wn*32 + nf*8 + 2*lc;
            *(float2*)(Ob + (size_t)row0*CC + col) =
                make_float2(acc[mf][nf][0], acc[mf][nf][1]);
            *(float2*)(Ob + (size_t)(row0+8)*CC + col) =
                make_float2(acc[mf][nf][2], acc[mf][nf][3]);
        }
    }
}

// ---------------- K6: tf32 mma conv: out = Wo(beta*Y + X) + bo ------------------
// dyn smem: Wt[2][128*36] | Vt[2][128*36] fp32  = 73728 B
#define KF_SMEM (4*128*36*4)
__global__ void __launch_bounds__(256, 2) k_final_mma(
    const float* __restrict__ x, const float* __restrict__ wo,
    const float* __restrict__ bo, const float* __restrict__ beta,
    float* __restrict__ out)
{
    extern __shared__ float smf[];
    float* Wt0 = smf;
    float* Vt0 = smf + 2*128*APAD;

    const int tid  = threadIdx.x;
    const int lane = tid & 31;
    const int warp = tid >> 5;
    const int wm   = warp & 1;
    const int wn   = warp >> 1;
    const int lr   = lane >> 2;
    const int lc   = lane & 3;
    const int n0   = blockIdx.x * 128;
    const int b    = blockIdx.y;
    const int kz   = blockIdx.z;
    const float bt = beta[0];
    const float* xb = x + (size_t)b*CC*NN;
    const float* Yb = g_O[b];

    float acc[4][4][4];
    #pragma unroll
    for (int mf = 0; mf < 4; mf++)
        #pragma unroll
        for (int nf = 0; nf < 4; nf++)
            #pragma unroll
            for (int q = 0; q < 4; q++) acc[mf][nf][q] = 0.f;

    const int xt = tid & 127, xch = tid >> 7;

    #define STAGE_F(s, c0) do {                                                 \
        float* Wt = Wt0 + (s)*128*APAD;                                         \
        float* Vt = Vt0 + (s)*128*APAD;                                         \
        _Pragma("unroll")                                                       \
        for (int r = 0; r < 16; r++) {                                          \
            int idx = tid + 256*r;                                              \
            int k = idx >> 5, c = idx & 31;                                     \
            Wt[k*APAD + c] = to_tf32f(wo[(kz*128 + k)*CC + (c0) + c]);          \
        }                                                                       \
        _Pragma("unroll")                                                       \
        for (int r = 0; r < 16; r++) {                                          \
            int c = xch*16 + r;                                                 \
            size_t off = (size_t)((c0) + c)*NN + n0 + xt;                       \
            Vt[xt*APAD + c] = to_tf32f(fmaf(bt, Yb[off], xb[off]));             \
        }                                                                       \
    } while (0)

    STAGE_F(0, 0);
    __syncthreads();

    for (int ch = 0; ch < 8; ch++) {
        const int s = ch & 1;
        if (ch + 1 < 8) STAGE_F(s^1, (ch+1)*32);

        const float* Wt = Wt0 + s*128*APAD;
        const float* Vt = Vt0 + s*128*APAD;
        #pragma unroll
        for (int ks = 0; ks < 4; ks++) {
            const int mb8 = ks * 8;
            uint32_t afr[4][4], bfr[4][2];
            #pragma unroll
            for (int mf = 0; mf < 4; mf++) {
                const float* ap = &Wt[(wm*64 + mf*16 + lr)*APAD + mb8 + lc];
                afr[mf][0] = __float_as_uint(ap[0]);
                afr[mf][1] = __float_as_uint(ap[8*APAD]);
                afr[mf][2] = __float_as_uint(ap[4]);
                afr[mf][3] = __float_as_uint(ap[8*APAD + 4]);
            }
            #pragma unroll
            for (int nf = 0; nf < 4; nf++) {
                const float* bp = &Vt[(wn*32 + nf*8 + lr)*APAD + mb8 + lc];
                bfr[nf][0] = __float_as_uint(bp[0]);
                bfr[nf][1] = __float_as_uint(bp[4]);
            }
            #pragma unroll
            for (int mf = 0; mf < 4; mf++)
                #pragma unroll
                for (int nf = 0; nf < 4; nf++)
                    mma_tf32(acc[mf][nf], afr[mf], bfr[nf]);
        }
        __syncthreads();
    }

    #pragma unroll
    for (int mf = 0; mf < 4; mf++) {
        int krow = kz*128 + wm*64 + mf*16 + lr;
        float b0 = __ldg(bo + krow), b8 = __ldg(bo + krow + 8);
        #pragma unroll
        for (int nf = 0; nf < 4; nf++) {
            int col = n0 + wn*32 + nf*8 + 2*lc;
            *(float2*)(out + ((size_t)b*CC + krow)*NN + col) =
                make_float2(acc[mf][nf][0] + b0, acc[mf][nf][1] + b0);
            *(float2*)(out + ((size_t)b*CC + krow + 8)*NN + col) =
                make_float2(acc[mf][nf][2] + b8, acc[mf][nf][3] + b8);
        }
    }
}

// ---------------- launch --------------------------------------------------------
extern "C" void kernel_launch(void* const* d_in, const int* in_sizes, int n_in,
                              void* d_out, int out_size)
{
    const float* x    = (const float*)d_in[0];
    const float* wa   = (const float*)d_in[1];
    const float* ba   = (const float*)d_in[2];
    const float* wb   = (const float*)d_in[3];
    const float* bb   = (const float*)d_in[4];
    const float* wc   = (const float*)d_in[5];
    const float* bc   = (const float*)d_in[6];
    const float* wo   = (const float*)d_in[7];
    const float* bo   = (const float*)d_in[8];
    const float* beta = (const float*)d_in[9];
    float* out = (float*)d_out;

    cudaFuncSetAttribute(k_pt_e,      cudaFuncAttributeMaxDynamicSharedMemorySize, PTE_SMEM);
    cudaFuncSetAttribute(k_out_bf16,  cudaFuncAttributeMaxDynamicSharedMemorySize, KO_SMEM);
    cudaFuncSetAttribute(k_final_mma, cudaFuncAttributeMaxDynamicSharedMemorySize, KF_SMEM);

    k_zero     <<<(BB*NN + 1023)/1024, 1024>>>();
    k_ab       <<<dim3(NN/256, BB, 2),      256>>>(x, wa, ba, wb, bb);
    k_norm     <<<BB, 256>>>();
    k_pt_e     <<<dim3(NN/128, NN/128, BB), 256, PTE_SMEM>>>();
    k_c_mma    <<<dim3(NN/128, BB, 2),      256>>>(x, wc, bc);
    k_out_bf16 <<<dim3(NN/128, BB), 512, KO_SMEM>>>();
    k_final_mma<<<dim3(NN/128, BB, 2),      256, KF_SMEM>>>(x, wo, bo, beta, out);
}

// round 7
// speedup vs baseline: 5.3849x; 1.0841x over previous
#include <cuda_runtime.h>
#include <cuda_bf16.h>
#include <math.h>
#include <stdint.h>

#define BB  8
#define CC  256
#define MIDD 32
#define NN  4096

// ---------------- scratch ----------------------------------------------------
__device__ float g_A  [BB][MIDD*NN];
__device__ float g_Bm [BB][MIDD*NN];
__device__ float g_mx [BB];
__device__ float g_Zs [BB*NN];
__device__ __nv_bfloat16 g_CsH[BB][CC*NN];        // (WcX+bc)/Z  [k][j] bf16
__device__ float g_O  [BB][NN*CC];                // out [i][k] (== Y[c][n] flat)

__device__ __forceinline__ uint32_t smem_u32(const void* p) {
    uint32_t a;
    asm("{ .reg .u64 t; cvta.to.shared.u64 t, %1; cvt.u32.u64 %0, t; }" : "=r"(a) : "l"(p));
    return a;
}
__device__ __forceinline__ uint32_t pk_bf2(float a, float b) {
    __nv_bfloat162 h = __floats2bfloat162_rn(a, b);
    return *(uint32_t*)&h;
}
__device__ __forceinline__ float to_tf32f(float f) {
    uint32_t u;
    asm("cvt.rna.tf32.f32 %0, %1;" : "=r"(u) : "f"(f));
    return __uint_as_float(u);
}
#define CP16(dst, src) asm volatile("cp.async.cg.shared.global [%0], [%1], 16;" :: "r"(dst), "l"(src))
#define CP_COMMIT()    asm volatile("cp.async.commit_group;" ::: "memory")
#define CP_WAIT(n)     asm volatile("cp.async.wait_group %0;" :: "n"(n) : "memory")

__device__ __forceinline__ void mma_bf16(float* c, const uint32_t* a, const uint32_t* b) {
    asm volatile(
        "mma.sync.aligned.m16n8k16.row.col.f32.bf16.bf16.f32 "
        "{%0,%1,%2,%3}, {%4,%5,%6,%7}, {%8,%9}, {%0,%1,%2,%3};"
        : "+f"(c[0]), "+f"(c[1]), "+f"(c[2]), "+f"(c[3])
        : "r"(a[0]), "r"(a[1]), "r"(a[2]), "r"(a[3]), "r"(b[0]), "r"(b[1]));
}
__device__ __forceinline__ void mma_tf32(float* c, const uint32_t* a, const uint32_t* b) {
    asm volatile(
        "mma.sync.aligned.m16n8k8.row.col.f32.tf32.tf32.f32 "
        "{%0,%1,%2,%3}, {%4,%5,%6,%7}, {%8,%9}, {%0,%1,%2,%3};"
        : "+f"(c[0]), "+f"(c[1]), "+f"(c[2]), "+f"(c[3])
        : "r"(a[0]), "r"(a[1]), "r"(a[2]), "r"(a[3]), "r"(b[0]), "r"(b[1]));
}

// ---------------- K1: A = WaX+ba, B = WbX+bb ----------------------------------
__global__ void k_ab(const float* __restrict__ x,
                     const float* __restrict__ wa, const float* __restrict__ ba,
                     const float* __restrict__ wb, const float* __restrict__ bb)
{
    __shared__ float ws[MIDD*CC];
    __shared__ float bs[MIDD];
    const int b = blockIdx.y;
    const int which = blockIdx.z;
    const float* w    = which ? wb : wa;
    const float* bias = which ? bb : ba;
    float* outp       = which ? g_Bm[b] : g_A[b];

    for (int i = threadIdx.x; i < MIDD*CC; i += 256) ws[i] = w[i];
    if (threadIdx.x < MIDD) bs[threadIdx.x] = bias[threadIdx.x];
    __syncthreads();

    const int n = blockIdx.x*256 + threadIdx.x;
    const float* xb = x + (size_t)b*CC*NN;
    float acc[MIDD];
    #pragma unroll
    for (int m = 0; m < MIDD; m++) acc[m] = bs[m];
    for (int c = 0; c < CC; c++) {
        float xv = xb[c*NN + n];
        #pragma unroll
        for (int m = 0; m < MIDD; m++) acc[m] += ws[m*CC + c] * xv;
    }
    #pragma unroll
    for (int m = 0; m < MIDD; m++) outp[m*NN + n] = acc[m];
}

// ---------------- K2: per-batch bound m = max||a|| * max||b|| -------------------
__global__ void k_norm() {
    const int b = blockIdx.x;
    const int t = threadIdx.x;
    const float* A  = g_A [b];
    const float* Bm = g_Bm[b];
    float ma = 0.f, mb = 0.f;
    for (int i = t; i < NN; i += 256) {
        float sa = 0.f, sb = 0.f;
        #pragma unroll
        for (int m = 0; m < MIDD; m++) {
            float av = A [m*NN + i]; sa += av*av;
            float bv = Bm[m*NN + i]; sb += bv*bv;
        }
        ma = fmaxf(ma, sa); mb = fmaxf(mb, sb);
    }
    __shared__ float ra[256], rb[256];
    ra[t] = ma; rb[t] = mb; __syncthreads();
    for (int s = 128; s > 0; s >>= 1) {
        if (t < s) { ra[t] = fmaxf(ra[t], ra[t+s]); rb[t] = fmaxf(rb[t], rb[t+s]); }
        __syncthreads();
    }
    if (t == 0) g_mx[b] = sqrtf(ra[0]) * sqrtf(rb[0]);
}

// ---------------- K3: k_z — Z[j] only (no E materialization) --------------------
// Block owns 128 j for one batch; loops 32 i-chunks of 128 (double-buffered A).
#define APAD 36
#define KZ_SMEM ((3*128*APAD + 128) * 4)   // 55808 B

__global__ void __launch_bounds__(256, 2) k_z()
{
    extern __shared__ float smf[];
    float* Bs  = smf;                        // [128 j][36]
    float* As0 = smf + 128*APAD;             // [2][128 i][36]
    float* Zsm = smf + 3*128*APAD;           // [128]

    const int b  = blockIdx.y;
    const int j0 = blockIdx.x * 128;
    const float* A  = g_A [b];
    const float* Bm = g_Bm[b];
    const int tid  = threadIdx.x;
    const int lane = tid & 31;
    const int warp = tid >> 5;
    const int wm   = warp & 1;        // i half
    const int wn   = warp >> 1;       // j quarter
    const int lr   = lane >> 2;
    const int lc   = lane & 3;

    for (int idx = tid; idx < 128*MIDD; idx += 256) {
        int m = idx >> 7, t = idx & 127;
        Bs[t*APAD + m] = to_tf32f(Bm[m*NN + j0 + t]);
    }
    if (tid < 128) Zsm[tid] = 0.f;
    #pragma unroll
    for (int r = 0; r < 16; r++) {
        int idx = tid + 256*r;
        int m = idx >> 7, t = idx & 127;
        As0[t*APAD + m] = to_tf32f(A[m*NN + t]);
    }
    __syncthreads();

    const float mbv = g_mx[b];
    float z0[4], z1[4];
    #pragma unroll
    for (int nf = 0; nf < 4; nf++) { z0[nf] = 0.f; z1[nf] = 0.f; }

    for (int ic = 0; ic < 32; ic++) {
        const int s = ic & 1;
        const float* As = As0 + s*128*APAD;
        if (ic + 1 < 32) {
            float* An = As0 + (s^1)*128*APAD;
            const int ib = (ic+1)*128;
            #pragma unroll
            for (int r = 0; r < 16; r++) {
                int idx = tid + 256*r;
                int m = idx >> 7, t = idx & 127;
                An[t*APAD + m] = to_tf32f(A[m*NN + ib + t]);
            }
        }

        float acc[4][4][4];
        #pragma unroll
        for (int mf = 0; mf < 4; mf++)
            #pragma unroll
            for (int nf = 0; nf < 4; nf++)
                #pragma unroll
                for (int q = 0; q < 4; q++) acc[mf][nf][q] = 0.f;

        #pragma unroll
        for (int ks = 0; ks < 4; ks++) {
            const int mb8 = ks * 8;
            uint32_t afr[4][4], bfr[4][2];
            #pragma unroll
            for (int mf = 0; mf < 4; mf++) {
                const float* ap = &As[(wm*64 + mf*16 + lr)*APAD + mb8 + lc];
                afr[mf][0] = __float_as_uint(ap[0]);
                afr[mf][1] = __float_as_uint(ap[8*APAD]);
                afr[mf][2] = __float_as_uint(ap[4]);
                afr[mf][3] = __float_as_uint(ap[8*APAD + 4]);
            }
            #pragma unroll
            for (int nf = 0; nf < 4; nf++) {
                const float* bp = &Bs[(wn*32 + nf*8 + lr)*APAD + mb8 + lc];
                bfr[nf][0] = __float_as_uint(bp[0]);
                bfr[nf][1] = __float_as_uint(bp[4]);
            }
            #pragma unroll
            for (int mf = 0; mf < 4; mf++)
                #pragma unroll
                for (int nf = 0; nf < 4; nf++)
                    mma_tf32(acc[mf][nf], afr[mf], bfr[nf]);
        }

        #pragma unroll
        for (int mf = 0; mf < 4; mf++)
            #pragma unroll
            for (int nf = 0; nf < 4; nf++) {
                z0[nf] += __expf(acc[mf][nf][0] - mbv) + __expf(acc[mf][nf][2] - mbv);
                z1[nf] += __expf(acc[mf][nf][1] - mbv) + __expf(acc[mf][nf][3] - mbv);
            }
        __syncthreads();
    }

    #pragma unroll
    for (int nf = 0; nf < 4; nf++) {
        float s0 = z0[nf], s1 = z1[nf];
        #pragma unroll
        for (int msk = 4; msk <= 16; msk <<= 1) {
            s0 += __shfl_xor_sync(0xFFFFFFFF, s0, msk);
            s1 += __shfl_xor_sync(0xFFFFFFFF, s1, msk);
        }
        if (lr == 0) {
            atomicAdd(&Zsm[wn*32 + nf*8 + 2*lc],     s0);
            atomicAdd(&Zsm[wn*32 + nf*8 + 2*lc + 1], s1);
        }
    }
    __syncthreads();
    if (tid < 128) g_Zs[b*NN + j0 + tid] = Zsm[tid];
}

// ---------------- K4: bf16 mma conv: CsH[k][n] = (Wc X + bc)[k][n] / Z[n] -------
#define KCPAD 40
__global__ void __launch_bounds__(256, 2) k_c_mma(
    const float* __restrict__ x, const float* __restrict__ wc,
    const float* __restrict__ bc)
{
    __shared__ __nv_bfloat16 Wt[2][128*KCPAD];
    __shared__ __nv_bfloat16 Xt[2][128*KCPAD];

    const int tid  = threadIdx.x;
    const int lane = tid & 31;
    const int warp = tid >> 5;
    const int wm   = warp & 1;
    const int wn   = warp >> 1;
    const int lr   = lane >> 2;
    const int lc   = lane & 3;
    const int n0   = blockIdx.x * 128;
    const int b    = blockIdx.y;
    const int kz   = blockIdx.z;
    const float* xb = x + (size_t)b*CC*NN;

    float acc[4][4][4];
    #pragma unroll
    for (int mf = 0; mf < 4; mf++)
        #pragma unroll
        for (int nf = 0; nf < 4; nf++)
            #pragma unroll
            for (int q = 0; q < 4; q++) acc[mf][nf][q] = 0.f;

    const int xt = tid & 127, xch = tid >> 7;

    #define STAGE_C(s, c0) do {                                                 \
        _Pragma("unroll")                                                       \
        for (int r = 0; r < 8; r++) {                                           \
            int idx = tid + 256*r;                                              \
            int k = idx >> 4, cp = idx & 15;                                    \
            float2 w2 = *(const float2*)(wc + (kz*128 + k)*CC + (c0) + cp*2);   \
            *(uint32_t*)&Wt[s][k*KCPAD + cp*2] = pk_bf2(w2.x, w2.y);            \
        }                                                                       \
        _Pragma("unroll")                                                       \
        for (int r = 0; r < 16; r++) {                                          \
            int c = xch*16 + r;                                                 \
            Xt[s][xt*KCPAD + c] =                                               \
                __float2bfloat16(xb[(size_t)((c0) + c)*NN + n0 + xt]);          \
        }                                                                       \
    } while (0)

    STAGE_C(0, 0);
    __syncthreads();

    for (int ch = 0; ch < 8; ch++) {
        const int s = ch & 1;
        if (ch + 1 < 8) STAGE_C(s^1, (ch+1)*32);

        #pragma unroll
        for (int ks = 0; ks < 2; ks++) {
            const int jb = ks * 16;
            uint32_t afr[4][4], bfr[4][2];
            #pragma unroll
            for (int mf = 0; mf < 4; mf++) {
                const __nv_bfloat16* ap = &Wt[s][(wm*64 + mf*16 + lr)*KCPAD + jb + 2*lc];
                afr[mf][0] = *(const uint32_t*)(ap);
                afr[mf][1] = *(const uint32_t*)(ap + 8*KCPAD);
                afr[mf][2] = *(const uint32_t*)(ap + 8);
                afr[mf][3] = *(const uint32_t*)(ap + 8*KCPAD + 8);
            }
            #pragma unroll
            for (int nf = 0; nf < 4; nf++) {
                const __nv_bfloat16* bp = &Xt[s][(wn*32 + nf*8 + lr)*KCPAD + jb + 2*lc];
                bfr[nf][0] = *(const uint32_t*)(bp);
                bfr[nf][1] = *(const uint32_t*)(bp + 8);
            }
            #pragma unroll
            for (int mf = 0; mf < 4; mf++)
                #pragma unroll
                for (int nf = 0; nf < 4; nf++)
                    mma_bf16(acc[mf][nf], afr[mf], bfr[nf]);
        }
        __syncthreads();
    }

    const float* Zb = &g_Zs[b*NN];
    float iz0[4], iz1[4];
    #pragma unroll
    for (int nf = 0; nf < 4; nf++) {
        int col = n0 + wn*32 + nf*8 + 2*lc;
        iz0[nf] = 1.f / Zb[col];
        iz1[nf] = 1.f / Zb[col+1];
    }
    __nv_bfloat16* Cb = g_CsH[b];
    #pragma unroll
    for (int mf = 0; mf < 4; mf++) {
        int krow = kz*128 + wm*64 + mf*16 + lr;
        float bc0 = __ldg(bc + krow), bc8 = __ldg(bc + krow + 8);
        #pragma unroll
        for (int nf = 0; nf < 4; nf++) {
            int col = n0 + wn*32 + nf*8 + 2*lc;
            *(uint32_t*)(Cb + (size_t)krow*NN + col) =
                pk_bf2((acc[mf][nf][0] + bc0)*iz0[nf], (acc[mf][nf][1] + bc0)*iz1[nf]);
            *(uint32_t*)(Cb + (size_t)(krow+8)*NN + col) =
                pk_bf2((acc[mf][nf][2] + bc8)*iz0[nf], (acc[mf][nf][3] + bc8)*iz1[nf]);
        }
    }
}

// ---------------- K5: fused out[i][k] = sum_j exp(a_i.b_j - m) * CsH[k][j] ------
// 512 thr. Per block: A-tile staged once; per 64-j chunk: recompute logits (tf32
// mma, 4x4 warps), exp -> bf16 smem, then main bf16 mma (2x8 warps).
#define EROW2 144
#define OF_BT 18432
#define OF_ET 36864
#define OF_CS 55296
#define CSB   36864
#define KOF_SMEM 129024

__global__ void __launch_bounds__(512, 1) k_out_f()
{
    extern __shared__ char sm[];
    float* As = (float*)sm;                              // [128 i][36]
    const uint32_t sb = smem_u32(sm);
    const int tid  = threadIdx.x;
    const int lane = tid & 31;
    const int warp = tid >> 5;
    const int wm   = warp & 1;    // main: M half
    const int wn   = warp >> 1;   // main: N eighth
    const int wi   = warp & 3;    // logit: i quarter
    const int wj   = warp >> 2;   // logit: j quarter
    const int lr   = lane >> 2;
    const int lc   = lane & 3;
    const int b    = blockIdx.y;
    const int i0   = blockIdx.x * 128;

    const float* A  = g_A [b];
    const float* Bm = g_Bm[b];
    const __nv_bfloat16* Ch = g_CsH[b];
    const float mbv = g_mx[b];

    #pragma unroll
    for (int r = 0; r < 8; r++) {
        int idx = tid + 512*r;
        int m = idx >> 7, t = idx & 127;
        As[t*APAD + m] = to_tf32f(A[m*NN + i0 + t]);
    }

    float acc[4][4][4];
    #pragma unroll
    for (int mf = 0; mf < 4; mf++)
        #pragma unroll
        for (int nf = 0; nf < 4; nf++)
            #pragma unroll
            for (int q = 0; q < 4; q++) acc[mf][nf][q] = 0.f;

    #define ISSUE_CS(ch, s) do {                                                \
        uint32_t cb = sb + OF_CS + (s)*CSB;                                     \
        int _j = (ch)*64;                                                       \
        _Pragma("unroll")                                                       \
        for (int r = 0; r < 4; r++) {                                           \
            int id = tid + 512*r; int row = id >> 3, q = id & 7;                \
            CP16(cb + row*EROW2 + q*16,                                         \
                 (const char*)(Ch + (size_t)row*NN + _j) + q*16);               \
        }                                                                       \
        CP_COMMIT();                                                            \
    } while (0)

    ISSUE_CS(0, 0);
    __syncthreads();

    const int bj  = tid & 63;
    const int bm0 = (tid >> 6) * 4;

    for (int ch = 0; ch < 64; ch++) {
        const int s = ch & 1;
        const int j0c = ch * 64;

        // stage B chunk [64 j][32 m] tf32
        float* Bt = (float*)(sm + OF_BT) + s*64*APAD;
        #pragma unroll
        for (int q = 0; q < 4; q++)
            Bt[bj*APAD + bm0 + q] = to_tf32f(Bm[(bm0 + q)*NN + j0c + bj]);

        if (ch + 1 < 64) { ISSUE_CS(ch+1, s^1); CP_WAIT(1); }
        else             { CP_WAIT(0); }
        __syncthreads();

        // logit mma: [128 i x 64 j]
        float lacc[2][2][4];
        #pragma unroll
        for (int mf = 0; mf < 2; mf++)
            #pragma unroll
            for (int nf = 0; nf < 2; nf++)
                #pragma unroll
                for (int q = 0; q < 4; q++) lacc[mf][nf][q] = 0.f;

        #pragma unroll
        for (int ks = 0; ks < 4; ks++) {
            const int mb8 = ks * 8;
            uint32_t afr[2][4], bfr[2][2];
            #pragma unroll
            for (int mf = 0; mf < 2; mf++) {
                const float* ap = &As[(wi*32 + mf*16 + lr)*APAD + mb8 + lc];
                afr[mf][0] = __float_as_uint(ap[0]);
                afr[mf][1] = __float_as_uint(ap[8*APAD]);
                afr[mf][2] = __float_as_uint(ap[4]);
                afr[mf][3] = __float_as_uint(ap[8*APAD + 4]);
            }
            #pragma unroll
            for (int nf = 0; nf < 2; nf++) {
                const float* bp = &Bt[(wj*16 + nf*8 + lr)*APAD + mb8 + lc];
                bfr[nf][0] = __float_as_uint(bp[0]);
                bfr[nf][1] = __float_as_uint(bp[4]);
            }
            #pragma unroll
            for (int mf = 0; mf < 2; mf++)
                #pragma unroll
                for (int nf = 0; nf < 2; nf++)
                    mma_tf32(lacc[mf][nf], afr[mf], bfr[nf]);
        }

        // exp -> Et (bf16 [128][64], row stride 144B)
        uint32_t* Et = (uint32_t*)(sm + OF_ET);
        #pragma unroll
        for (int mf = 0; mf < 2; mf++) {
            const int row = wi*32 + mf*16 + lr;
            #pragma unroll
            for (int nf = 0; nf < 2; nf++) {
                const int colu = wj*8 + nf*4 + lc;
                float e0 = __expf(lacc[mf][nf][0] - mbv);
                float e1 = __expf(lacc[mf][nf][1] - mbv);
                float e2 = __expf(lacc[mf][nf][2] - mbv);
                float e3 = __expf(lacc[mf][nf][3] - mbv);
                Et[row*36 + colu]     = pk_bf2(e0, e1);
                Et[(row+8)*36 + colu] = pk_bf2(e2, e3);
            }
        }
        __syncthreads();

        // main mma: 4 ksteps of 16 over the 64-j chunk
        const char* eb  = sm + OF_ET;
        const char* cbp = sm + OF_CS + s*CSB;
        #pragma unroll
        for (int ks = 0; ks < 4; ks++) {
            const int jb = ks * 16;
            uint32_t afr[4][4], bfr[4][2];
            #pragma unroll
            for (int mf = 0; mf < 4; mf++) {
                const char* a = eb + (wm*64 + mf*16 + lr)*EROW2 + (jb + 2*lc)*2;
                afr[mf][0] = *(const uint32_t*)(a);
                afr[mf][1] = *(const uint32_t*)(a + 8*EROW2);
                afr[mf][2] = *(const uint32_t*)(a + 16);
                afr[mf][3] = *(const uint32_t*)(a + 8*EROW2 + 16);
            }
            #pragma unroll
            for (int nf = 0; nf < 4; nf++) {
                const char* bq = cbp + (wn*32 + nf*8 + lr)*EROW2 + (jb + 2*lc)*2;
                bfr[nf][0] = *(const uint32_t*)(bq);
                bfr[nf][1] = *(const uint32_t*)(bq + 16);
            }
            #pragma unroll
            for (int mf = 0; mf < 4; mf++)
                #pragma unroll
                for (int nf = 0; nf < 4; nf++)
                    mma_bf16(acc[mf][nf], afr[mf], bfr[nf]);
        }
        __syncthreads();
    }

    float* Ob = g_O[b];
    #pragma unroll
    for (int mf = 0; mf < 4; mf++) {
        int row0 = i0 + wm*64 + mf*16 + lr;
        #pragma unroll
        for (int nf = 0; nf < 4; nf++) {
            int col = wn*32 + nf*8 + 2*lc;
            *(float2*)(Ob + (size_t)row0*CC + col) =
                make_float2(acc[mf][nf][0], acc[mf][nf][1]);
            *(float2*)(Ob + (size_t)(row0+8)*CC + col) =
                make_float2(acc[mf][nf][2], acc[mf][nf][3]);
        }
    }
}

// ---------------- K6: tf32 mma conv: out = Wo(beta*Y + X) + bo ------------------
#define KF_SMEM (4*128*APAD*4)
__global__ void __launch_bounds__(256, 2) k_final_mma(
    const float* __restrict__ x, const float* __restrict__ wo,
    const float* __restrict__ bo, const float* __restrict__ beta,
    float* __restrict__ out)
{
    extern __shared__ float smf[];
    float* Wt0 = smf;
    float* Vt0 = smf + 2*128*APAD;

    const int tid  = threadIdx.x;
    const int lane = tid & 31;
    const int warp = tid >> 5;
    const int wm   = warp & 1;
    const int wn   = warp >> 1;
    const int lr   = lane >> 2;
    const int lc   = lane & 3;
    const int n0   = blockIdx.x * 128;
    const int b    = blockIdx.y;
    const int kz   = blockIdx.z;
    const float bt = beta[0];
    const float* xb = x + (size_t)b*CC*NN;
    const float* Yb = g_O[b];

    float acc[4][4][4];
    #pragma unroll
    for (int mf = 0; mf < 4; mf++)
        #pragma unroll
        for (int nf = 0; nf < 4; nf++)
            #pragma unroll
            for (int q = 0; q < 4; q++) acc[mf][nf][q] = 0.f;

    const int xt = tid & 127, xch = tid >> 7;

    #define STAGE_F(s, c0) do {                                                 \
        float* Wt = Wt0 + (s)*128*APAD;                                         \
        float* Vt = Vt0 + (s)*128*APAD;                                         \
        _Pragma("unroll")                                                       \
        for (int r = 0; r < 16; r++) {                                          \
            int idx = tid + 256*r;                                              \
            int k = idx >> 5, c = idx & 31;                                     \
            Wt[k*APAD + c] = to_tf32f(wo[(kz*128 + k)*CC + (c0) + c]);          \
        }                                                                       \
        _Pragma("unroll")                                                       \
        for (int r = 0; r < 16; r++) {                                          \
            int c = xch*16 + r;                                                 \
            size_t off = (size_t)((c0) + c)*NN + n0 + xt;                       \
            Vt[xt*APAD + c] = to_tf32f(fmaf(bt, Yb[off], xb[off]));             \
        }                                                                       \
    } while (0)

    STAGE_F(0, 0);
    __syncthreads();

    for (int ch = 0; ch < 8; ch++) {
        const int s = ch & 1;
        if (ch + 1 < 8) STAGE_F(s^1, (ch+1)*32);

        const float* Wt = Wt0 + s*128*APAD;
        const float* Vt = Vt0 + s*128*APAD;
        #pragma unroll
        for (int ks = 0; ks < 4; ks++) {
            const int mb8 = ks * 8;
            uint32_t afr[4][4], bfr[4][2];
            #pragma unroll
            for (int mf = 0; mf < 4; mf++) {
                const float* ap = &Wt[(wm*64 + mf*16 + lr)*APAD + mb8 + lc];
                afr[mf][0] = __float_as_uint(ap[0]);
                afr[mf][1] = __float_as_uint(ap[8*APAD]);
                afr[mf][2] = __float_as_uint(ap[4]);
                afr[mf][3] = __float_as_uint(ap[8*APAD + 4]);
            }
            #pragma unroll
            for (int nf = 0; nf < 4; nf++) {
                const float* bp = &Vt[(wn*32 + nf*8 + lr)*APAD + mb8 + lc];
                bfr[nf][0] = __float_as_uint(bp[0]);
                bfr[nf][1] = __float_as_uint(bp[4]);
            }
            #pragma unroll
            for (int mf = 0; mf < 4; mf++)
                #pragma unroll
                for (int nf = 0; nf < 4; nf++)
                    mma_tf32(acc[mf][nf], afr[mf], bfr[nf]);
        }
        __syncthreads();
    }

    #pragma unroll
    for (int mf = 0; mf < 4; mf++) {
        int krow = kz*128 + wm*64 + mf*16 + lr;
        float b0 = __ldg(bo + krow), b8 = __ldg(bo + krow + 8);
        #pragma unroll
        for (int nf = 0; nf < 4; nf++) {
            int col = n0 + wn*32 + nf*8 + 2*lc;
            *(float2*)(out + ((size_t)b*CC + krow)*NN + col) =
                make_float2(acc[mf][nf][0] + b0, acc[mf][nf][1] + b0);
            *(float2*)(out + ((size_t)b*CC + krow + 8)*NN + col) =
                make_float2(acc[mf][nf][2] + b8, acc[mf][nf][3] + b8);
        }
    }
}

// ---------------- launch --------------------------------------------------------
extern "C" void kernel_launch(void* const* d_in, const int* in_sizes, int n_in,
                              void* d_out, int out_size)
{
    const float* x    = (const float*)d_in[0];
    const float* wa   = (const float*)d_in[1];
    const float* ba   = (const float*)d_in[2];
    const float* wb   = (const float*)d_in[3];
    const float* bb   = (const float*)d_in[4];
    const float* wc   = (const float*)d_in[5];
    const float* bc   = (const float*)d_in[6];
    const float* wo   = (const float*)d_in[7];
    const float* bo   = (const float*)d_in[8];
    const float* beta = (const float*)d_in[9];
    float* out = (float*)d_out;

    cudaFuncSetAttribute(k_z,         cudaFuncAttributeMaxDynamicSharedMemorySize, KZ_SMEM);
    cudaFuncSetAttribute(k_out_f,     cudaFuncAttributeMaxDynamicSharedMemorySize, KOF_SMEM);
    cudaFuncSetAttribute(k_final_mma, cudaFuncAttributeMaxDynamicSharedMemorySize, KF_SMEM);

    k_ab       <<<dim3(NN/256, BB, 2),  256>>>(x, wa, ba, wb, bb);
    k_norm     <<<BB, 256>>>();
    k_z        <<<dim3(NN/128, BB),     256, KZ_SMEM>>>();
    k_c_mma    <<<dim3(NN/128, BB, 2),  256>>>(x, wc, bc);
    k_out_f    <<<dim3(NN/128, BB),     512, KOF_SMEM>>>();
    k_final_mma<<<dim3(NN/128, BB, 2),  256, KF_SMEM>>>(x, wo, bo, beta, out);
}

// round 8
// speedup vs baseline: 5.5416x; 1.0291x over previous
#include <cuda_runtime.h>
#include <cuda_bf16.h>
#include <math.h>
#include <stdint.h>

#define BB  8
#define CC  256
#define MIDD 32
#define NN  4096

// ---------------- scratch ----------------------------------------------------
__device__ float g_A  [BB][MIDD*NN];
__device__ float g_Bm [BB][MIDD*NN];
__device__ float g_mx [BB];
__device__ float g_Zs [BB*NN];
__device__ __nv_bfloat16 g_CsH[BB][CC*NN];        // (WcX+bc)/Z  [k][j] bf16
__device__ float g_O  [BB][NN*CC];                // out [i][k] (== Y[c][n] flat)

__device__ __forceinline__ uint32_t smem_u32(const void* p) {
    uint32_t a;
    asm("{ .reg .u64 t; cvta.to.shared.u64 t, %1; cvt.u32.u64 %0, t; }" : "=r"(a) : "l"(p));
    return a;
}
__device__ __forceinline__ uint32_t pk_bf2(float a, float b) {
    __nv_bfloat162 h = __floats2bfloat162_rn(a, b);
    return *(uint32_t*)&h;
}
__device__ __forceinline__ float to_tf32f(float f) {
    uint32_t u;
    asm("cvt.rna.tf32.f32 %0, %1;" : "=r"(u) : "f"(f));
    return __uint_as_float(u);
}
#define CP16(dst, src) asm volatile("cp.async.cg.shared.global [%0], [%1], 16;" :: "r"(dst), "l"(src))
#define CP_COMMIT()    asm volatile("cp.async.commit_group;" ::: "memory")
#define CP_WAIT(n)     asm volatile("cp.async.wait_group %0;" :: "n"(n) : "memory")

__device__ __forceinline__ void mma_bf16(float* c, const uint32_t* a, const uint32_t* b) {
    asm volatile(
        "mma.sync.aligned.m16n8k16.row.col.f32.bf16.bf16.f32 "
        "{%0,%1,%2,%3}, {%4,%5,%6,%7}, {%8,%9}, {%0,%1,%2,%3};"
        : "+f"(c[0]), "+f"(c[1]), "+f"(c[2]), "+f"(c[3])
        : "r"(a[0]), "r"(a[1]), "r"(a[2]), "r"(a[3]), "r"(b[0]), "r"(b[1]));
}
__device__ __forceinline__ void mma_tf32(float* c, const uint32_t* a, const uint32_t* b) {
    asm volatile(
        "mma.sync.aligned.m16n8k8.row.col.f32.tf32.tf32.f32 "
        "{%0,%1,%2,%3}, {%4,%5,%6,%7}, {%8,%9}, {%0,%1,%2,%3};"
        : "+f"(c[0]), "+f"(c[1]), "+f"(c[2]), "+f"(c[3])
        : "r"(a[0]), "r"(a[1]), "r"(a[2]), "r"(a[3]), "r"(b[0]), "r"(b[1]));
}

// ---------------- K1: A = WaX+ba, B = WbX+bb ----------------------------------
__global__ void k_ab(const float* __restrict__ x,
                     const float* __restrict__ wa, const float* __restrict__ ba,
                     const float* __restrict__ wb, const float* __restrict__ bb)
{
    __shared__ float ws[MIDD*CC];
    __shared__ float bs[MIDD];
    const int b = blockIdx.y;
    const int which = blockIdx.z;
    const float* w    = which ? wb : wa;
    const float* bias = which ? bb : ba;
    float* outp       = which ? g_Bm[b] : g_A[b];

    for (int i = threadIdx.x; i < MIDD*CC; i += 256) ws[i] = w[i];
    if (threadIdx.x < MIDD) bs[threadIdx.x] = bias[threadIdx.x];
    __syncthreads();

    const int n = blockIdx.x*256 + threadIdx.x;
    const float* xb = x + (size_t)b*CC*NN;
    float acc[MIDD];
    #pragma unroll
    for (int m = 0; m < MIDD; m++) acc[m] = bs[m];
    for (int c = 0; c < CC; c++) {
        float xv = xb[c*NN + n];
        #pragma unroll
        for (int m = 0; m < MIDD; m++) acc[m] += ws[m*CC + c] * xv;
    }
    #pragma unroll
    for (int m = 0; m < MIDD; m++) outp[m*NN + n] = acc[m];
}

// ---------------- K2: per-batch bound m = max||a|| * max||b|| -------------------
__global__ void k_norm() {
    const int b = blockIdx.x;
    const int t = threadIdx.x;
    const float* A  = g_A [b];
    const float* Bm = g_Bm[b];
    float ma = 0.f, mb = 0.f;
    for (int i = t; i < NN; i += 256) {
        float sa = 0.f, sb = 0.f;
        #pragma unroll
        for (int m = 0; m < MIDD; m++) {
            float av = A [m*NN + i]; sa += av*av;
            float bv = Bm[m*NN + i]; sb += bv*bv;
        }
        ma = fmaxf(ma, sa); mb = fmaxf(mb, sb);
    }
    __shared__ float ra[256], rb[256];
    ra[t] = ma; rb[t] = mb; __syncthreads();
    for (int s = 128; s > 0; s >>= 1) {
        if (t < s) { ra[t] = fmaxf(ra[t], ra[t+s]); rb[t] = fmaxf(rb[t], rb[t+s]); }
        __syncthreads();
    }
    if (t == 0) g_mx[b] = sqrtf(ra[0]) * sqrtf(rb[0]);
}

// ---------------- K3: k_z — Z[j] only (no E materialization) --------------------
#define APAD 36
#define KZ_SMEM ((3*128*APAD + 128) * 4)

__global__ void __launch_bounds__(256, 2) k_z()
{
    extern __shared__ float smf[];
    float* Bs  = smf;
    float* As0 = smf + 128*APAD;
    float* Zsm = smf + 3*128*APAD;

    const int b  = blockIdx.y;
    const int j0 = blockIdx.x * 128;
    const float* A  = g_A [b];
    const float* Bm = g_Bm[b];
    const int tid  = threadIdx.x;
    const int lane = tid & 31;
    const int warp = tid >> 5;
    const int wm   = warp & 1;
    const int wn   = warp >> 1;
    const int lr   = lane >> 2;
    const int lc   = lane & 3;

    for (int idx = tid; idx < 128*MIDD; idx += 256) {
        int m = idx >> 7, t = idx & 127;
        Bs[t*APAD + m] = to_tf32f(Bm[m*NN + j0 + t]);
    }
    if (tid < 128) Zsm[tid] = 0.f;
    #pragma unroll
    for (int r = 0; r < 16; r++) {
        int idx = tid + 256*r;
        int m = idx >> 7, t = idx & 127;
        As0[t*APAD + m] = to_tf32f(A[m*NN + t]);
    }
    __syncthreads();

    const float mbv = g_mx[b];
    float z0[4], z1[4];
    #pragma unroll
    for (int nf = 0; nf < 4; nf++) { z0[nf] = 0.f; z1[nf] = 0.f; }

    for (int ic = 0; ic < 32; ic++) {
        const int s = ic & 1;
        const float* As = As0 + s*128*APAD;
        if (ic + 1 < 32) {
            float* An = As0 + (s^1)*128*APAD;
            const int ib = (ic+1)*128;
            #pragma unroll
            for (int r = 0; r < 16; r++) {
                int idx = tid + 256*r;
                int m = idx >> 7, t = idx & 127;
                An[t*APAD + m] = to_tf32f(A[m*NN + ib + t]);
            }
        }

        float acc[4][4][4];
        #pragma unroll
        for (int mf = 0; mf < 4; mf++)
            #pragma unroll
            for (int nf = 0; nf < 4; nf++)
                #pragma unroll
                for (int q = 0; q < 4; q++) acc[mf][nf][q] = 0.f;

        #pragma unroll
        for (int ks = 0; ks < 4; ks++) {
            const int mb8 = ks * 8;
            uint32_t afr[4][4], bfr[4][2];
            #pragma unroll
            for (int mf = 0; mf < 4; mf++) {
                const float* ap = &As[(wm*64 + mf*16 + lr)*APAD + mb8 + lc];
                afr[mf][0] = __float_as_uint(ap[0]);
                afr[mf][1] = __float_as_uint(ap[8*APAD]);
                afr[mf][2] = __float_as_uint(ap[4]);
                afr[mf][3] = __float_as_uint(ap[8*APAD + 4]);
            }
            #pragma unroll
            for (int nf = 0; nf < 4; nf++) {
                const float* bp = &Bs[(wn*32 + nf*8 + lr)*APAD + mb8 + lc];
                bfr[nf][0] = __float_as_uint(bp[0]);
                bfr[nf][1] = __float_as_uint(bp[4]);
            }
            #pragma unroll
            for (int mf = 0; mf < 4; mf++)
                #pragma unroll
                for (int nf = 0; nf < 4; nf++)
                    mma_tf32(acc[mf][nf], afr[mf], bfr[nf]);
        }

        #pragma unroll
        for (int mf = 0; mf < 4; mf++)
            #pragma unroll
            for (int nf = 0; nf < 4; nf++) {
                z0[nf] += __expf(acc[mf][nf][0] - mbv) + __expf(acc[mf][nf][2] - mbv);
                z1[nf] += __expf(acc[mf][nf][1] - mbv) + __expf(acc[mf][nf][3] - mbv);
            }
        __syncthreads();
    }

    #pragma unroll
    for (int nf = 0; nf < 4; nf++) {
        float s0 = z0[nf], s1 = z1[nf];
        #pragma unroll
        for (int msk = 4; msk <= 16; msk <<= 1) {
            s0 += __shfl_xor_sync(0xFFFFFFFF, s0, msk);
            s1 += __shfl_xor_sync(0xFFFFFFFF, s1, msk);
        }
        if (lr == 0) {
            atomicAdd(&Zsm[wn*32 + nf*8 + 2*lc],     s0);
            atomicAdd(&Zsm[wn*32 + nf*8 + 2*lc + 1], s1);
        }
    }
    __syncthreads();
    if (tid < 128) g_Zs[b*NN + j0 + tid] = Zsm[tid];
}

// ---------------- K4: bf16 mma conv: CsH[k][n] = (Wc X + bc)[k][n] / Z[n] -------
#define KCPAD 40
__global__ void __launch_bounds__(256, 2) k_c_mma(
    const float* __restrict__ x, const float* __restrict__ wc,
    const float* __restrict__ bc)
{
    __shared__ __nv_bfloat16 Wt[2][128*KCPAD];
    __shared__ __nv_bfloat16 Xt[2][128*KCPAD];

    const int tid  = threadIdx.x;
    const int lane = tid & 31;
    const int warp = tid >> 5;
    const int wm   = warp & 1;
    const int wn   = warp >> 1;
    const int lr   = lane >> 2;
    const int lc   = lane & 3;
    const int n0   = blockIdx.x * 128;
    const int b    = blockIdx.y;
    const int kz   = blockIdx.z;
    const float* xb = x + (size_t)b*CC*NN;

    float acc[4][4][4];
    #pragma unroll
    for (int mf = 0; mf < 4; mf++)
        #pragma unroll
        for (int nf = 0; nf < 4; nf++)
            #pragma unroll
            for (int q = 0; q < 4; q++) acc[mf][nf][q] = 0.f;

    const int xt = tid & 127, xch = tid >> 7;

    #define STAGE_C(s, c0) do {                                                 \
        _Pragma("unroll")                                                       \
        for (int r = 0; r < 8; r++) {                                           \
            int idx = tid + 256*r;                                              \
            int k = idx >> 4, cp = idx & 15;                                    \
            float2 w2 = *(const float2*)(wc + (kz*128 + k)*CC + (c0) + cp*2);   \
            *(uint32_t*)&Wt[s][k*KCPAD + cp*2] = pk_bf2(w2.x, w2.y);            \
        }                                                                       \
        _Pragma("unroll")                                                       \
        for (int r = 0; r < 16; r++) {                                          \
            int c = xch*16 + r;                                                 \
            Xt[s][xt*KCPAD + c] =                                               \
                __float2bfloat16(xb[(size_t)((c0) + c)*NN + n0 + xt]);          \
        }                                                                       \
    } while (0)

    STAGE_C(0, 0);
    __syncthreads();

    for (int ch = 0; ch < 8; ch++) {
        const int s = ch & 1;
        if (ch + 1 < 8) STAGE_C(s^1, (ch+1)*32);

        #pragma unroll
        for (int ks = 0; ks < 2; ks++) {
            const int jb = ks * 16;
            uint32_t afr[4][4], bfr[4][2];
            #pragma unroll
            for (int mf = 0; mf < 4; mf++) {
                const __nv_bfloat16* ap = &Wt[s][(wm*64 + mf*16 + lr)*KCPAD + jb + 2*lc];
                afr[mf][0] = *(const uint32_t*)(ap);
                afr[mf][1] = *(const uint32_t*)(ap + 8*KCPAD);
                afr[mf][2] = *(const uint32_t*)(ap + 8);
                afr[mf][3] = *(const uint32_t*)(ap + 8*KCPAD + 8);
            }
            #pragma unroll
            for (int nf = 0; nf < 4; nf++) {
                const __nv_bfloat16* bp = &Xt[s][(wn*32 + nf*8 + lr)*KCPAD + jb + 2*lc];
                bfr[nf][0] = *(const uint32_t*)(bp);
                bfr[nf][1] = *(const uint32_t*)(bp + 8);
            }
            #pragma unroll
            for (int mf = 0; mf < 4; mf++)
                #pragma unroll
                for (int nf = 0; nf < 4; nf++)
                    mma_bf16(acc[mf][nf], afr[mf], bfr[nf]);
        }
        __syncthreads();
    }

    const float* Zb = &g_Zs[b*NN];
    float iz0[4], iz1[4];
    #pragma unroll
    for (int nf = 0; nf < 4; nf++) {
        int col = n0 + wn*32 + nf*8 + 2*lc;
        iz0[nf] = 1.f / Zb[col];
        iz1[nf] = 1.f / Zb[col+1];
    }
    __nv_bfloat16* Cb = g_CsH[b];
    #pragma unroll
    for (int mf = 0; mf < 4; mf++) {
        int krow = kz*128 + wm*64 + mf*16 + lr;
        float bc0 = __ldg(bc + krow), bc8 = __ldg(bc + krow + 8);
        #pragma unroll
        for (int nf = 0; nf < 4; nf++) {
            int col = n0 + wn*32 + nf*8 + 2*lc;
            *(uint32_t*)(Cb + (size_t)krow*NN + col) =
                pk_bf2((acc[mf][nf][0] + bc0)*iz0[nf], (acc[mf][nf][1] + bc0)*iz1[nf]);
            *(uint32_t*)(Cb + (size_t)(krow+8)*NN + col) =
                pk_bf2((acc[mf][nf][2] + bc8)*iz0[nf], (acc[mf][nf][3] + bc8)*iz1[nf]);
        }
    }
}

// ---------------- K5: fused, software-pipelined: ONE sync per chunk -------------
// smem: As[128][36]f32 | Bt 2x[64][36]f32 | Et 2x[128x144B] | Cs 2x[256x144B]
#define EROW2 144
#define OF_BT 18432
#define OF_ET 36864
#define OF_CS 73728
#define ETB   18432
#define CSB   36864
#define BTF   (64*APAD)
#define KOF_SMEM 147456

__global__ void __launch_bounds__(512, 1) k_out_f()
{
    extern __shared__ char sm[];
    float* As = (float*)sm;
    const uint32_t sb = smem_u32(sm);
    const int tid  = threadIdx.x;
    const int lane = tid & 31;
    const int warp = tid >> 5;
    const int wm   = warp & 1;    // main: M half
    const int wn   = warp >> 1;   // main: N eighth
    const int wi   = warp & 3;    // logit: i quarter
    const int wj   = warp >> 2;   // logit: j quarter
    const int lr   = lane >> 2;
    const int lc   = lane & 3;
    const int b    = blockIdx.y;
    const int i0   = blockIdx.x * 128;

    const float* A  = g_A [b];
    const float* Bm = g_Bm[b];
    const __nv_bfloat16* Ch = g_CsH[b];
    const float mbv = g_mx[b];

    const int bj  = tid & 63;
    const int bm0 = (tid >> 6) * 4;

    #define ISSUE_CS(ch, s) do {                                                \
        uint32_t cb = sb + OF_CS + (s)*CSB;                                     \
        int _j = (ch)*64;                                                       \
        _Pragma("unroll")                                                       \
        for (int r = 0; r < 4; r++) {                                           \
            int id = tid + 512*r; int row = id >> 3, q = id & 7;                \
            CP16(cb + row*EROW2 + q*16,                                         \
                 (const char*)(Ch + (size_t)row*NN + _j) + q*16);               \
        }                                                                       \
        CP_COMMIT();                                                            \
    } while (0)

    #define STAGE_BT(s, ch) do {                                                \
        float* Bt = (float*)(sm + OF_BT) + (s)*BTF;                             \
        int _j = (ch)*64;                                                       \
        _Pragma("unroll")                                                       \
        for (int q = 0; q < 4; q++)                                             \
            Bt[bj*APAD + bm0 + q] = to_tf32f(Bm[(bm0 + q)*NN + _j + bj]);       \
    } while (0)

    #define LOGIT_MMA(lacc, s) do {                                             \
        const float* Bt = (const float*)(sm + OF_BT) + (s)*BTF;                 \
        _Pragma("unroll")                                                       \
        for (int mf = 0; mf < 2; mf++)                                          \
            _Pragma("unroll")                                                   \
            for (int nf = 0; nf < 2; nf++)                                      \
                _Pragma("unroll")                                               \
                for (int q = 0; q < 4; q++) lacc[mf][nf][q] = 0.f;              \
        _Pragma("unroll")                                                       \
        for (int ks = 0; ks < 4; ks++) {                                        \
            const int mb8 = ks * 8;                                             \
            uint32_t afr[2][4], bfr[2][2];                                      \
            _Pragma("unroll")                                                   \
            for (int mf = 0; mf < 2; mf++) {                                    \
                const float* ap = &As[(wi*32 + mf*16 + lr)*APAD + mb8 + lc];    \
                afr[mf][0] = __float_as_uint(ap[0]);                            \
                afr[mf][1] = __float_as_uint(ap[8*APAD]);                       \
                afr[mf][2] = __float_as_uint(ap[4]);                            \
                afr[mf][3] = __float_as_uint(ap[8*APAD + 4]);                   \
            }                                                                   \
            _Pragma("unroll")                                                   \
            for (int nf = 0; nf < 2; nf++) {                                    \
                const float* bp = &Bt[(wj*16 + nf*8 + lr)*APAD + mb8 + lc];     \
                bfr[nf][0] = __float_as_uint(bp[0]);                            \
                bfr[nf][1] = __float_as_uint(bp[4]);                            \
            }                                                                   \
            _Pragma("unroll")                                                   \
            for (int mf = 0; mf < 2; mf++)                                      \
                _Pragma("unroll")                                               \
                for (int nf = 0; nf < 2; nf++)                                  \
                    mma_tf32(lacc[mf][nf], afr[mf], bfr[nf]);                   \
        }                                                                       \
    } while (0)

    #define EXP_STORE(lacc, s) do {                                             \
        uint32_t* Et = (uint32_t*)(sm + OF_ET + (s)*ETB);                       \
        _Pragma("unroll")                                                       \
        for (int mf = 0; mf < 2; mf++) {                                        \
            const int row = wi*32 + mf*16 + lr;                                 \
            _Pragma("unroll")                                                   \
            for (int nf = 0; nf < 2; nf++) {                                    \
                const int colu = wj*8 + nf*4 + lc;                              \
                float e0 = __expf(lacc[mf][nf][0] - mbv);                       \
                float e1 = __expf(lacc[mf][nf][1] - mbv);                       \
                float e2 = __expf(lacc[mf][nf][2] - mbv);                       \
                float e3 = __expf(lacc[mf][nf][3] - mbv);                       \
                Et[row*36 + colu]     = pk_bf2(e0, e1);                         \
                Et[(row+8)*36 + colu] = pk_bf2(e2, e3);                         \
            }                                                                   \
        }                                                                       \
    } while (0)

    // ---- prologue ----
    #pragma unroll
    for (int r = 0; r < 8; r++) {
        int idx = tid + 512*r;
        int m = idx >> 7, t = idx & 127;
        As[t*APAD + m] = to_tf32f(A[m*NN + i0 + t]);
    }
    STAGE_BT(0, 0);
    ISSUE_CS(0, 0);
    CP_WAIT(0);
    __syncthreads();                      // As, Bt[0], Cs[0] ready

    {
        float lacc[2][2][4];
        LOGIT_MMA(lacc, 0);
        EXP_STORE(lacc, 0);
    }
    STAGE_BT(1, 1);
    __syncthreads();                      // Et[0], Bt[1] ready
    ISSUE_CS(1, 1);

    float acc[4][4][4];
    #pragma unroll
    for (int mf = 0; mf < 4; mf++)
        #pragma unroll
        for (int nf = 0; nf < 4; nf++)
            #pragma unroll
            for (int q = 0; q < 4; q++) acc[mf][nf][q] = 0.f;

    // ---- main loop: one sync per chunk ----
    for (int ch = 0; ch < 64; ch++) {
        const int s = ch & 1;

        // main mma on chunk ch (Et[s], Cs[s])
        const char* eb  = sm + OF_ET + s*ETB;
        const char* cbp = sm + OF_CS + s*CSB;
        #pragma unroll
        for (int ks = 0; ks < 4; ks++) {
            const int jb = ks * 16;
            uint32_t afr[4][4], bfr[4][2];
            #pragma unroll
            for (int mf = 0; mf < 4; mf++) {
                const char* a = eb + (wm*64 + mf*16 + lr)*EROW2 + (jb + 2*lc)*2;
                afr[mf][0] = *(const uint32_t*)(a);
                afr[mf][1] = *(const uint32_t*)(a + 8*EROW2);
                afr[mf][2] = *(const uint32_t*)(a + 16);
                afr[mf][3] = *(const uint32_t*)(a + 8*EROW2 + 16);
            }
            #pragma unroll
            for (int nf = 0; nf < 4; nf++) {
                const char* bq = cbp + (wn*32 + nf*8 + lr)*EROW2 + (jb + 2*lc)*2;
                bfr[nf][0] = *(const uint32_t*)(bq);
                bfr[nf][1] = *(const uint32_t*)(bq + 16);
            }
            #pragma unroll
            for (int mf = 0; mf < 4; mf++)
                #pragma unroll
                for (int nf = 0; nf < 4; nf++)
                    mma_bf16(acc[mf][nf], afr[mf], bfr[nf]);
        }

        if (ch + 1 < 64) {
            // next-chunk logits overlap laggard warps' main mma
            float lacc[2][2][4];
            LOGIT_MMA(lacc, s^1);
            EXP_STORE(lacc, s^1);
            if (ch + 2 < 64) STAGE_BT(s, ch+2);
            CP_WAIT(0);                   // Cs[s^1] landed (group ch+1)
            __syncthreads();              // Et[s^1], Bt[s] visible; Cs[s] reads done
            if (ch + 2 < 64) ISSUE_CS(ch+2, s);   // safe: all Cs[s] reads fenced
        }
    }

    float* Ob = g_O[b];
    #pragma unroll
    for (int mf = 0; mf < 4; mf++) {
        int row0 = i0 + wm*64 + mf*16 + lr;
        #pragma unroll
        for (int nf = 0; nf < 4; nf++) {
            int col = wn*32 + nf*8 + 2*lc;
            *(float2*)(Ob + (size_t)row0*CC + col) =
                make_float2(acc[mf][nf][0], acc[mf][nf][1]);
            *(float2*)(Ob + (size_t)(row0+8)*CC + col) =
                make_float2(acc[mf][nf][2], acc[mf][nf][3]);
        }
    }
}

// ---------------- K6: tf32 mma conv: out = Wo(beta*Y + X) + bo ------------------
#define KF_SMEM (4*128*APAD*4)
__global__ void __launch_bounds__(256, 2) k_final_mma(
    const float* __restrict__ x, const float* __restrict__ wo,
    const float* __restrict__ bo, const float* __restrict__ beta,
    float* __restrict__ out)
{
    extern __shared__ float smf[];
    float* Wt0 = smf;
    float* Vt0 = smf + 2*128*APAD;

    const int tid  = threadIdx.x;
    const int lane = tid & 31;
    const int warp = tid >> 5;
    const int wm   = warp & 1;
    const int wn   = warp >> 1;
    const int lr   = lane >> 2;
    const int lc   = lane & 3;
    const int n0   = blockIdx.x * 128;
    const int b    = blockIdx.y;
    const int kz   = blockIdx.z;
    const float bt = beta[0];
    const float* xb = x + (size_t)b*CC*NN;
    const float* Yb = g_O[b];

    float acc[4][4][4];
    #pragma unroll
    for (int mf = 0; mf < 4; mf++)
        #pragma unroll
        for (int nf = 0; nf < 4; nf++)
            #pragma unroll
            for (int q = 0; q < 4; q++) acc[mf][nf][q] = 0.f;

    const int xt = tid & 127, xch = tid >> 7;

    #define STAGE_F(s, c0) do {                                                 \
        float* Wt = Wt0 + (s)*128*APAD;                                         \
        float* Vt = Vt0 + (s)*128*APAD;                                         \
        _Pragma("unroll")                                                       \
        for (int r = 0; r < 16; r++) {                                          \
            int idx = tid + 256*r;                                              \
            int k = idx >> 5, c = idx & 31;                                     \
            Wt[k*APAD + c] = to_tf32f(wo[(kz*128 + k)*CC + (c0) + c]);          \
        }                                                                       \
        _Pragma("unroll")                                                       \
        for (int r = 0; r < 16; r++) {                                          \
            int c = xch*16 + r;                                                 \
            size_t off = (size_t)((c0) + c)*NN + n0 + xt;                       \
            Vt[xt*APAD + c] = to_tf32f(fmaf(bt, Yb[off], xb[off]));             \
        }                                                                       \
    } while (0)

    STAGE_F(0, 0);
    __syncthreads();

    for (int ch = 0; ch < 8; ch++) {
        const int s = ch & 1;
        if (ch + 1 < 8) STAGE_F(s^1, (ch+1)*32);

        const float* Wt = Wt0 + s*128*APAD;
        const float* Vt = Vt0 + s*128*APAD;
        #pragma unroll
        for (int ks = 0; ks < 4; ks++) {
            const int mb8 = ks * 8;
            uint32_t afr[4][4], bfr[4][2];
            #pragma unroll
            for (int mf = 0; mf < 4; mf++) {
                const float* ap = &Wt[(wm*64 + mf*16 + lr)*APAD + mb8 + lc];
                afr[mf][0] = __float_as_uint(ap[0]);
                afr[mf][1] = __float_as_uint(ap[8*APAD]);
                afr[mf][2] = __float_as_uint(ap[4]);
                afr[mf][3] = __float_as_uint(ap[8*APAD + 4]);
            }
            #pragma unroll
            for (int nf = 0; nf < 4; nf++) {
                const float* bp = &Vt[(wn*32 + nf*8 + lr)*APAD + mb8 + lc];
                bfr[nf][0] = __float_as_uint(bp[0]);
                bfr[nf][1] = __float_as_uint(bp[4]);
            }
            #pragma unroll
            for (int mf = 0; mf < 4; mf++)
                #pragma unroll
                for (int nf = 0; nf < 4; nf++)
                    mma_tf32(acc[mf][nf], afr[mf], bfr[nf]);
        }
        __syncthreads();
    }

    #pragma unroll
    for (int mf = 0; mf < 4; mf++) {
        int krow = kz*128 + wm*64 + mf*16 + lr;
        float b0 = __ldg(bo + krow), b8 = __ldg(bo + krow + 8);
        #pragma unroll
        for (int nf = 0; nf < 4; nf++) {
            int col = n0 + wn*32 + nf*8 + 2*lc;
            *(float2*)(out + ((size_t)b*CC + krow)*NN + col) =
                make_float2(acc[mf][nf][0] + b0, acc[mf][nf][1] + b0);
            *(float2*)(out + ((size_t)b*CC + krow + 8)*NN + col) =
                make_float2(acc[mf][nf][2] + b8, acc[mf][nf][3] + b8);
        }
    }
}

// ---------------- launch --------------------------------------------------------
extern "C" void kernel_launch(void* const* d_in, const int* in_sizes, int n_in,
                              void* d_out, int out_size)
{
    const float* x    = (const float*)d_in[0];
    const float* wa   = (const float*)d_in[1];
    const float* ba   = (const float*)d_in[2];
    const float* wb   = (const float*)d_in[3];
    const float* bb   = (const float*)d_in[4];
    const float* wc   = (const float*)d_in[5];
    const float* bc   = (const float*)d_in[6];
    const float* wo   = (const float*)d_in[7];
    const float* bo   = (const float*)d_in[8];
    const float* beta = (const float*)d_in[9];
    float* out = (float*)d_out;

    cudaFuncSetAttribute(k_z,         cudaFuncAttributeMaxDynamicSharedMemorySize, KZ_SMEM);
    cudaFuncSetAttribute(k_out_f,     cudaFuncAttributeMaxDynamicSharedMemorySize, KOF_SMEM);
    cudaFuncSetAttribute(k_final_mma, cudaFuncAttributeMaxDynamicSharedMemorySize, KF_SMEM);

    k_ab       <<<dim3(NN/256, BB, 2),  256>>>(x, wa, ba, wb, bb);
    k_norm     <<<BB, 256>>>();
    k_z        <<<dim3(NN/128, BB),     256, KZ_SMEM>>>();
    k_c_mma    <<<dim3(NN/128, BB, 2),  256>>>(x, wc, bc);
    k_out_f    <<<dim3(NN/128, BB),     512, KOF_SMEM>>>();
    k_final_mma<<<dim3(NN/128, BB, 2),  256, KF_SMEM>>>(x, wo, bo, beta, out);
}